// round 1
// baseline (speedup 1.0000x reference)
#include <cuda_runtime.h>

#define BB 4
#define NN 2048
#define CC 1024
#define HH 16
#define DD 64
#define MM (BB*NN)          // 8192
#define ROWS_PER (MM*HH)    // 131072 rows of 64 per tensor

// Scratch: q, k, v in [b*H+h][n][64] layout
__device__ float g_q[(size_t)MM * CC];
__device__ float g_k[(size_t)MM * CC];
__device__ float g_v[(size_t)MM * CC];

// ---------------------------------------------------------------------------
// GEMM: Out[bh][n][d] = A[m][k] @ W[k][coloff+n0..] + bias, 64x64 tile, BK=16
// ---------------------------------------------------------------------------
__global__ __launch_bounds__(256) void gemm_kernel(
    const float* __restrict__ A, const float* __restrict__ W,
    const float* __restrict__ bias, int ldb, int coloff, int which)
{
    __shared__ float As[64][20];   // pad to 20 for STS spread, float4-aligned
    __shared__ float Bs[16][64];

    float* Out = (which == 0) ? g_q : (which == 1) ? g_k : g_v;

    int tid = threadIdx.x;
    int tx = tid & 15, ty = tid >> 4;
    int m0 = blockIdx.y << 6;
    int n0 = blockIdx.x << 6;

    int arow = tid >> 2, akq = tid & 3;    // A tile loader: 64 rows x 4 quads
    int brow = tid >> 4, bnq = tid & 15;   // B tile loader: 16 rows x 16 quads

    const float* Aptr = A + (size_t)(m0 + arow) * CC + (akq << 2);
    const float* Wptr = W + (size_t)brow * ldb + coloff + n0 + (bnq << 2);

    float c[4][4] = {};

    for (int k0 = 0; k0 < CC; k0 += 16) {
        float4 av = *(const float4*)(Aptr + k0);
        float4 bv = *(const float4*)(Wptr + (size_t)k0 * ldb);
        *(float4*)&As[arow][akq << 2] = av;
        *(float4*)&Bs[brow][bnq << 2] = bv;
        __syncthreads();

        #pragma unroll
        for (int kk = 0; kk < 16; kk += 4) {
            float4 a4[4], b4[4];
            #pragma unroll
            for (int i = 0; i < 4; i++)
                a4[i] = *(const float4*)&As[(ty << 2) + i][kk];
            #pragma unroll
            for (int dd = 0; dd < 4; dd++)
                b4[dd] = *(const float4*)&Bs[kk + dd][tx << 2];
            #pragma unroll
            for (int i = 0; i < 4; i++) {
                float aa[4] = {a4[i].x, a4[i].y, a4[i].z, a4[i].w};
                #pragma unroll
                for (int dd = 0; dd < 4; dd++) {
                    c[i][0] += aa[dd] * b4[dd].x;
                    c[i][1] += aa[dd] * b4[dd].y;
                    c[i][2] += aa[dd] * b4[dd].z;
                    c[i][3] += aa[dd] * b4[dd].w;
                }
            }
        }
        __syncthreads();
    }

    // Epilogue: bias + scatter into [bh][n][d]
    int b = m0 >> 11;         // / 2048
    int n = m0 & 2047;
    int h = n0 >> 6;          // one head per 64-col tile
    float4 bb = *(const float4*)&bias[coloff + n0 + (tx << 2)];
    size_t obase = (((size_t)b * HH + h) * NN + n) * DD + (tx << 2);
    #pragma unroll
    for (int i = 0; i < 4; i++) {
        float4 vo = make_float4(c[i][0] + bb.x, c[i][1] + bb.y,
                                c[i][2] + bb.z, c[i][3] + bb.w);
        *(float4*)&Out[obase + (size_t)((ty << 2) + i) * DD] = vo;
    }
}

// ---------------------------------------------------------------------------
// LayerNorm over D=64 for q and k, one warp per row, in place
// ---------------------------------------------------------------------------
__global__ __launch_bounds__(256) void ln_kernel(
    const float* __restrict__ gq, const float* __restrict__ betq,
    const float* __restrict__ gk, const float* __restrict__ betk)
{
    int gwarp = (blockIdx.x * blockDim.x + threadIdx.x) >> 5;
    int lane = threadIdx.x & 31;

    float* arr; const float* gamma; const float* beta; size_t row;
    if (gwarp < ROWS_PER) { arr = g_q; gamma = gq; beta = betq; row = gwarp; }
    else                  { arr = g_k; gamma = gk; beta = betk; row = gwarp - ROWS_PER; }

    float2 x = *(const float2*)&arr[row * 64 + (lane << 1)];
    float s = x.x + x.y;
    #pragma unroll
    for (int o = 16; o >= 1; o >>= 1) s += __shfl_xor_sync(0xffffffffu, s, o);
    float mean = s * 0.015625f;
    float dx = x.x - mean, dy = x.y - mean;
    float v = dx * dx + dy * dy;
    #pragma unroll
    for (int o = 16; o >= 1; o >>= 1) v += __shfl_xor_sync(0xffffffffu, v, o);
    float inv = rsqrtf(v * 0.015625f + 1e-5f);
    float2 r;
    r.x = dx * inv * gamma[lane << 1]       + beta[lane << 1];
    r.y = dy * inv * gamma[(lane << 1) + 1] + beta[(lane << 1) + 1];
    *(float2*)&arr[row * 64 + (lane << 1)] = r;
}

// ---------------------------------------------------------------------------
// Flash attention: 64-row Q tile/block, stream 64-row K/V tiles, online softmax
// ---------------------------------------------------------------------------
__global__ __launch_bounds__(256) void attn_kernel(float* __restrict__ out)
{
    extern __shared__ float smem[];
    float* Qs = smem;            // [64][64]
    float* KP = smem + 4096;     // K^T [d][c], reused as P [r][m]
    float* Vs = smem + 8192;     // [m][c]

    int bh = blockIdx.y;         // 0..63
    int qt = blockIdx.x;         // 0..31
    int tid = threadIdx.x, tx = tid & 15, ty = tid >> 4;

    const float* qb = g_q + (size_t)bh * (NN * 64) + (size_t)qt * 4096;
    const float* kb = g_k + (size_t)bh * (NN * 64);
    const float* vb = g_v + (size_t)bh * (NN * 64);

    // Q tile is a contiguous 4096-float block
    for (int e = tid; e < 1024; e += 256)
        ((float4*)Qs)[e] = ((const float4*)qb)[e];

    float m_i[4], l_i[4], o[4][4];
    #pragma unroll
    for (int i = 0; i < 4; i++) {
        m_i[i] = -1e30f; l_i[i] = 0.f;
        #pragma unroll
        for (int j = 0; j < 4; j++) o[i][j] = 0.f;
    }

    for (int kt = 0; kt < 32; kt++) {
        __syncthreads();   // protect KP/Vs overwrite vs prior iter reads (and Q load at kt=0)

        const float* ks = kb + kt * 4096;
        const float4* vsrc = (const float4*)(vb + kt * 4096);
        for (int e = tid; e < 1024; e += 256) {
            int dq = e >> 6, c = e & 63;     // c spans 32/warp -> conflict-free STS
            float4 k4 = *(const float4*)(ks + c * 64 + (dq << 2));
            KP[((dq << 2) + 0) * 64 + c] = k4.x;
            KP[((dq << 2) + 1) * 64 + c] = k4.y;
            KP[((dq << 2) + 2) * 64 + c] = k4.z;
            KP[((dq << 2) + 3) * 64 + c] = k4.w;
            ((float4*)Vs)[e] = vsrc[e];
        }
        __syncthreads();

        // S = Q @ K^T
        float s[4][4] = {};
        #pragma unroll
        for (int d0 = 0; d0 < 64; d0 += 4) {
            float4 q4[4], k4[4];
            #pragma unroll
            for (int i = 0; i < 4; i++)
                q4[i] = *(const float4*)&Qs[((ty << 2) + i) * 64 + d0];
            #pragma unroll
            for (int dd = 0; dd < 4; dd++)
                k4[dd] = *(const float4*)&KP[(d0 + dd) * 64 + (tx << 2)];
            #pragma unroll
            for (int i = 0; i < 4; i++) {
                float qa[4] = {q4[i].x, q4[i].y, q4[i].z, q4[i].w};
                #pragma unroll
                for (int dd = 0; dd < 4; dd++) {
                    s[i][0] += qa[dd] * k4[dd].x;
                    s[i][1] += qa[dd] * k4[dd].y;
                    s[i][2] += qa[dd] * k4[dd].z;
                    s[i][3] += qa[dd] * k4[dd].w;
                }
            }
        }
        __syncthreads();   // all KP reads done; about to overwrite with P

        // Online softmax; row-mates = contiguous 16-lane group (shfl width 16)
        #pragma unroll
        for (int i = 0; i < 4; i++) {
            #pragma unroll
            for (int j = 0; j < 4; j++) s[i][j] *= 0.125f;   // 1/sqrt(64)
            float rm = fmaxf(fmaxf(s[i][0], s[i][1]), fmaxf(s[i][2], s[i][3]));
            #pragma unroll
            for (int off = 8; off >= 1; off >>= 1)
                rm = fmaxf(rm, __shfl_xor_sync(0xffffffffu, rm, off));
            float mn = fmaxf(m_i[i], rm);
            float alpha = __expf(m_i[i] - mn);
            float rs = 0.f;
            #pragma unroll
            for (int j = 0; j < 4; j++) {
                float p = __expf(s[i][j] - mn);
                s[i][j] = p; rs += p;
            }
            #pragma unroll
            for (int off = 8; off >= 1; off >>= 1)
                rs += __shfl_xor_sync(0xffffffffu, rs, off);
            m_i[i] = mn;
            l_i[i] = l_i[i] * alpha + rs;
            #pragma unroll
            for (int j = 0; j < 4; j++) o[i][j] *= alpha;
            *(float4*)&KP[((ty << 2) + i) * 64 + (tx << 2)] =
                make_float4(s[i][0], s[i][1], s[i][2], s[i][3]);
        }
        __syncthreads();

        // O += P @ V
        #pragma unroll
        for (int m0 = 0; m0 < 64; m0 += 4) {
            float4 p4[4], v4[4];
            #pragma unroll
            for (int i = 0; i < 4; i++)
                p4[i] = *(const float4*)&KP[((ty << 2) + i) * 64 + m0];
            #pragma unroll
            for (int dd = 0; dd < 4; dd++)
                v4[dd] = *(const float4*)&Vs[(m0 + dd) * 64 + (tx << 2)];
            #pragma unroll
            for (int i = 0; i < 4; i++) {
                float pa[4] = {p4[i].x, p4[i].y, p4[i].z, p4[i].w};
                #pragma unroll
                for (int dd = 0; dd < 4; dd++) {
                    o[i][0] += pa[dd] * v4[dd].x;
                    o[i][1] += pa[dd] * v4[dd].y;
                    o[i][2] += pa[dd] * v4[dd].z;
                    o[i][3] += pa[dd] * v4[dd].w;
                }
            }
        }
    }

    // Epilogue: normalize + write out[b][n][h*64+d]
    int b = bh >> 4, h = bh & 15;
    #pragma unroll
    for (int i = 0; i < 4; i++) {
        int n = (qt << 6) + (ty << 2) + i;
        float inv = 1.f / l_i[i];
        float4 vo = make_float4(o[i][0] * inv, o[i][1] * inv,
                                o[i][2] * inv, o[i][3] * inv);
        *(float4*)&out[((size_t)(b * NN + n)) * CC + (h << 6) + (tx << 2)] = vo;
    }
}

// ---------------------------------------------------------------------------
extern "C" void kernel_launch(void* const* d_in, const int* in_sizes, int n_in,
                              void* d_out, int out_size)
{
    const float* x1   = (const float*)d_in[0];
    const float* x2   = (const float*)d_in[1];
    const float* wq   = (const float*)d_in[2];
    const float* bq   = (const float*)d_in[3];
    const float* wkv  = (const float*)d_in[4];
    const float* bkv  = (const float*)d_in[5];
    const float* gmq  = (const float*)d_in[6];
    const float* btq  = (const float*)d_in[7];
    const float* gmk  = (const float*)d_in[8];
    const float* btk  = (const float*)d_in[9];
    float* out = (float*)d_out;

    cudaFuncSetAttribute(attn_kernel, cudaFuncAttributeMaxDynamicSharedMemorySize, 49152);

    dim3 gq_grid(CC / 64, MM / 64);    // 16 x 128
    gemm_kernel<<<gq_grid, 256>>>(x1, wq,  bq,  CC,     0,    0);  // -> g_q
    gemm_kernel<<<gq_grid, 256>>>(x2, wkv, bkv, 2 * CC, 0,    1);  // -> g_k
    gemm_kernel<<<gq_grid, 256>>>(x2, wkv, bkv, 2 * CC, CC,   2);  // -> g_v

    ln_kernel<<<(2 * ROWS_PER) / 8, 256>>>(gmq, btq, gmk, btk);

    attn_kernel<<<dim3(NN / 64, BB * HH), 256, 49152>>>(out);
}

// round 2
// speedup vs baseline: 2.3335x; 2.3335x over previous
#include <cuda_runtime.h>
#include <cstdint>

#define BB 4
#define NN 2048
#define CC 1024
#define HH 16
#define DD 64
#define MM (BB*NN)          // 8192
#define ROWS_PER (MM*HH)    // 131072 rows of 64 per tensor

// Scratch: q, k, v in [b*H+h][n][64] layout
__device__ float g_q[(size_t)MM * CC];
__device__ float g_k[(size_t)MM * CC];
__device__ float g_v[(size_t)MM * CC];

// ---------------------------------------------------------------------------
// helpers
// ---------------------------------------------------------------------------
__device__ __forceinline__ float f2tf(float x) {
    uint32_t u;
    asm("cvt.rna.tf32.f32 %0, %1;" : "=r"(u) : "f"(x));
    return __uint_as_float(u);
}

__device__ __forceinline__ void mma8(float c[4], const uint32_t a[4], const uint32_t b[2]) {
    asm volatile(
        "mma.sync.aligned.m16n8k8.row.col.f32.tf32.tf32.f32 "
        "{%0,%1,%2,%3}, {%4,%5,%6,%7}, {%8,%9}, {%0,%1,%2,%3};\n"
        : "+f"(c[0]), "+f"(c[1]), "+f"(c[2]), "+f"(c[3])
        : "r"(a[0]), "r"(a[1]), "r"(a[2]), "r"(a[3]), "r"(b[0]), "r"(b[1]));
}

// ---------------------------------------------------------------------------
// Projection GEMM (tf32 MMA): Out[bh][n][d] = A @ W[:, coloff+n0..] + bias
// Block tile 128x64, BK=32, 4 warps (2m x 2n), warp tile 64x32.
// ---------------------------------------------------------------------------
__global__ __launch_bounds__(128) void proj_kernel(
    const float* __restrict__ A, const float* __restrict__ W,
    const float* __restrict__ bias, int ldb, int coloff, int which)
{
    __shared__ float As[128][36];   // stride 36 ≡ 4 mod 32 -> conflict-free A frags
    __shared__ float Bs[32][72];    // stride 72 ≡ 8 mod 32 -> conflict-free B frags

    float* Out = (which == 0) ? g_q : (which == 1) ? g_k : g_v;

    int tid  = threadIdx.x;
    int wid  = tid >> 5, lane = tid & 31;
    int grp  = lane >> 2, l4 = lane & 3;
    int wm   = wid >> 1, wn = wid & 1;
    int m0   = blockIdx.y << 7;
    int head = blockIdx.x;
    int n0   = head << 6;

    float c[4][4][4];
    #pragma unroll
    for (int mf = 0; mf < 4; mf++)
        #pragma unroll
        for (int nf = 0; nf < 4; nf++)
            #pragma unroll
            for (int i = 0; i < 4; i++) c[mf][nf][i] = 0.f;

    int ar = tid >> 3, ac = tid & 7;     // A loader: 16 rows/pass x 8 float4
    int br = tid >> 4, bc = tid & 15;    // B loader: 8 rows/pass x 16 float4
    const float* Ap = A + (size_t)(m0 + ar) * CC + (ac << 2);
    const float* Wp = W + (size_t)br * ldb + coloff + n0 + (bc << 2);

    for (int k0 = 0; k0 < CC; k0 += 32) {
        #pragma unroll
        for (int i = 0; i < 8; i++) {
            float4 v = *(const float4*)(Ap + (size_t)(i << 4) * CC + k0);
            float* d = &As[ar + (i << 4)][ac << 2];
            d[0] = f2tf(v.x); d[1] = f2tf(v.y); d[2] = f2tf(v.z); d[3] = f2tf(v.w);
        }
        #pragma unroll
        for (int i = 0; i < 4; i++) {
            float4 v = *(const float4*)(Wp + (size_t)(k0 + (i << 3)) * ldb);
            float* d = &Bs[br + (i << 3)][bc << 2];
            d[0] = f2tf(v.x); d[1] = f2tf(v.y); d[2] = f2tf(v.z); d[3] = f2tf(v.w);
        }
        __syncthreads();

        #pragma unroll
        for (int ks = 0; ks < 4; ks++) {
            int k8 = ks << 3;
            uint32_t a[4][4], b[4][2];
            #pragma unroll
            for (int mf = 0; mf < 4; mf++) {
                int r = (wm << 6) + (mf << 4) + grp;
                a[mf][0] = __float_as_uint(As[r][k8 + l4]);
                a[mf][1] = __float_as_uint(As[r + 8][k8 + l4]);
                a[mf][2] = __float_as_uint(As[r][k8 + l4 + 4]);
                a[mf][3] = __float_as_uint(As[r + 8][k8 + l4 + 4]);
            }
            #pragma unroll
            for (int nf = 0; nf < 4; nf++) {
                int n = (wn << 5) + (nf << 3) + grp;
                b[nf][0] = __float_as_uint(Bs[k8 + l4][n]);
                b[nf][1] = __float_as_uint(Bs[k8 + l4 + 4][n]);
            }
            #pragma unroll
            for (int mf = 0; mf < 4; mf++)
                #pragma unroll
                for (int nf = 0; nf < 4; nf++)
                    mma8(c[mf][nf], a[mf], b[nf]);
        }
        __syncthreads();
    }

    // Epilogue: bias + scatter into [bh][n][d]
    int bidx = m0 >> 11;
    #pragma unroll
    for (int mf = 0; mf < 4; mf++) {
        int mrow = (wm << 6) + (mf << 4) + grp;
        int nseq = (m0 + mrow) & 2047;
        size_t base = (((size_t)(bidx * HH + head)) * NN + nseq) * DD;
        #pragma unroll
        for (int nf = 0; nf < 4; nf++) {
            int col = (wn << 5) + (nf << 3) + (l4 << 1);
            float bx = bias[coloff + n0 + col];
            float by = bias[coloff + n0 + col + 1];
            float2 v0 = make_float2(c[mf][nf][0] + bx, c[mf][nf][1] + by);
            float2 v1 = make_float2(c[mf][nf][2] + bx, c[mf][nf][3] + by);
            *(float2*)&Out[base + col] = v0;
            *(float2*)&Out[base + (size_t)8 * DD + col] = v1;
        }
    }
}

// ---------------------------------------------------------------------------
// LayerNorm over D=64 for q and k, one warp per row, in place
// ---------------------------------------------------------------------------
__global__ __launch_bounds__(256) void ln_kernel(
    const float* __restrict__ gq, const float* __restrict__ betq,
    const float* __restrict__ gk, const float* __restrict__ betk)
{
    int gwarp = (blockIdx.x * blockDim.x + threadIdx.x) >> 5;
    int lane = threadIdx.x & 31;

    float* arr; const float* gamma; const float* beta; size_t row;
    if (gwarp < ROWS_PER) { arr = g_q; gamma = gq; beta = betq; row = gwarp; }
    else                  { arr = g_k; gamma = gk; beta = betk; row = gwarp - ROWS_PER; }

    float2 x = *(const float2*)&arr[row * 64 + (lane << 1)];
    float s = x.x + x.y;
    #pragma unroll
    for (int o = 16; o >= 1; o >>= 1) s += __shfl_xor_sync(0xffffffffu, s, o);
    float mean = s * 0.015625f;
    float dx = x.x - mean, dy = x.y - mean;
    float v = dx * dx + dy * dy;
    #pragma unroll
    for (int o = 16; o >= 1; o >>= 1) v += __shfl_xor_sync(0xffffffffu, v, o);
    float inv = rsqrtf(v * 0.015625f + 1e-5f);
    float2 r;
    r.x = dx * inv * gamma[lane << 1]       + beta[lane << 1];
    r.y = dy * inv * gamma[(lane << 1) + 1] + beta[(lane << 1) + 1];
    *(float2*)&arr[row * 64 + (lane << 1)] = r;
}

// ---------------------------------------------------------------------------
// Flash attention (tf32 MMA): 128-row Q tile/block, 4 warps (32 q-rows each),
// stream 64-row K/V tiles, online softmax in fp32 fragments.
// ---------------------------------------------------------------------------
__global__ __launch_bounds__(128) void attn_kernel(float* __restrict__ out)
{
    extern __shared__ float sm[];
    float (*Qs)[68] = (float(*)[68])sm;                                // 128x68
    float (*Ks)[68] = (float(*)[68])(sm + 128 * 68);                   // 64x68 [key][d]
    float (*Vs)[72] = (float(*)[72])(sm + 128 * 68 + 64 * 68);         // 64x72 [key][d]
    float (*Ps)[68] = (float(*)[68])(sm + 128 * 68 + 64 * 68 + 64 * 72); // 128x68

    int tid = threadIdx.x;
    int wid = tid >> 5, lane = tid & 31;
    int grp = lane >> 2, l4 = lane & 3;
    int bh = blockIdx.y, qt = blockIdx.x;
    int mb = wid << 5;   // warp q-row base (0,32,64,96)

    const float* qb = g_q + (size_t)bh * (NN * 64) + (size_t)qt * (128 * 64);
    const float* kb = g_k + (size_t)bh * (NN * 64);
    const float* vb = g_v + (size_t)bh * (NN * 64);

    // load Q tile (128x64), tf32-rounded
    #pragma unroll
    for (int i = 0; i < 16; i++) {
        int f = i * 128 + tid;
        int r = f >> 4, cix = (f & 15) << 2;
        float4 v = *(const float4*)(qb + r * 64 + cix);
        Qs[r][cix] = f2tf(v.x); Qs[r][cix + 1] = f2tf(v.y);
        Qs[r][cix + 2] = f2tf(v.z); Qs[r][cix + 3] = f2tf(v.w);
    }

    float o[2][8][4];
    #pragma unroll
    for (int mf = 0; mf < 2; mf++)
        #pragma unroll
        for (int df = 0; df < 8; df++)
            #pragma unroll
            for (int i = 0; i < 4; i++) o[mf][df][i] = 0.f;
    float m_i[4] = {-1e30f, -1e30f, -1e30f, -1e30f};
    float l_i[4] = {0.f, 0.f, 0.f, 0.f};

    for (int kt = 0; kt < 32; kt++) {
        __syncthreads();   // prior-iter smem reads complete
        const float* ks = kb + kt * 4096;
        const float* vs = vb + kt * 4096;
        #pragma unroll
        for (int i = 0; i < 8; i++) {
            int f = i * 128 + tid;
            int r = f >> 4, cix = (f & 15) << 2;
            float4 kv = *(const float4*)(ks + r * 64 + cix);
            Ks[r][cix] = f2tf(kv.x); Ks[r][cix + 1] = f2tf(kv.y);
            Ks[r][cix + 2] = f2tf(kv.z); Ks[r][cix + 3] = f2tf(kv.w);
            float4 vv = *(const float4*)(vs + r * 64 + cix);
            Vs[r][cix] = f2tf(vv.x); Vs[r][cix + 1] = f2tf(vv.y);
            Vs[r][cix + 2] = f2tf(vv.z); Vs[r][cix + 3] = f2tf(vv.w);
        }
        __syncthreads();

        // S = Q @ K^T  (k-dim = d = 64)
        float s[2][8][4];
        #pragma unroll
        for (int mf = 0; mf < 2; mf++)
            #pragma unroll
            for (int nf = 0; nf < 8; nf++)
                #pragma unroll
                for (int i = 0; i < 4; i++) s[mf][nf][i] = 0.f;

        #pragma unroll
        for (int ks8 = 0; ks8 < 8; ks8++) {
            int k8 = ks8 << 3;
            uint32_t a[2][4], b[8][2];
            #pragma unroll
            for (int mf = 0; mf < 2; mf++) {
                int r = mb + (mf << 4) + grp;
                a[mf][0] = __float_as_uint(Qs[r][k8 + l4]);
                a[mf][1] = __float_as_uint(Qs[r + 8][k8 + l4]);
                a[mf][2] = __float_as_uint(Qs[r][k8 + l4 + 4]);
                a[mf][3] = __float_as_uint(Qs[r + 8][k8 + l4 + 4]);
            }
            #pragma unroll
            for (int nf = 0; nf < 8; nf++) {
                int n = (nf << 3) + grp;
                b[nf][0] = __float_as_uint(Ks[n][k8 + l4]);
                b[nf][1] = __float_as_uint(Ks[n][k8 + l4 + 4]);
            }
            #pragma unroll
            for (int mf = 0; mf < 2; mf++)
                #pragma unroll
                for (int nf = 0; nf < 8; nf++)
                    mma8(s[mf][nf], a[mf], b[nf]);
        }

        // online softmax (scale 1/8)
        #pragma unroll
        for (int mf = 0; mf < 2; mf++) {
            #pragma unroll
            for (int nf = 0; nf < 8; nf++)
                #pragma unroll
                for (int i = 0; i < 4; i++) s[mf][nf][i] *= 0.125f;

            #pragma unroll
            for (int rr = 0; rr < 2; rr++) {
                int si = (mf << 1) + rr;
                float mx = -1e30f;
                #pragma unroll
                for (int nf = 0; nf < 8; nf++)
                    mx = fmaxf(mx, fmaxf(s[mf][nf][rr * 2], s[mf][nf][rr * 2 + 1]));
                mx = fmaxf(mx, __shfl_xor_sync(0xffffffffu, mx, 1));
                mx = fmaxf(mx, __shfl_xor_sync(0xffffffffu, mx, 2));
                float mn = fmaxf(m_i[si], mx);
                float alpha = __expf(m_i[si] - mn);
                float rs = 0.f;
                #pragma unroll
                for (int nf = 0; nf < 8; nf++) {
                    float p0 = __expf(s[mf][nf][rr * 2] - mn);
                    float p1 = __expf(s[mf][nf][rr * 2 + 1] - mn);
                    s[mf][nf][rr * 2] = p0; s[mf][nf][rr * 2 + 1] = p1;
                    rs += p0 + p1;
                }
                rs += __shfl_xor_sync(0xffffffffu, rs, 1);
                rs += __shfl_xor_sync(0xffffffffu, rs, 2);
                m_i[si] = mn;
                l_i[si] = l_i[si] * alpha + rs;
                #pragma unroll
                for (int df = 0; df < 8; df++) {
                    o[mf][df][rr * 2] *= alpha;
                    o[mf][df][rr * 2 + 1] *= alpha;
                }
            }
            // write P fragment rows (tf32)
            int r = mb + (mf << 4) + grp;
            #pragma unroll
            for (int nf = 0; nf < 8; nf++) {
                int cix = (nf << 3) + (l4 << 1);
                Ps[r][cix]     = f2tf(s[mf][nf][0]);
                Ps[r][cix + 1] = f2tf(s[mf][nf][1]);
                Ps[r + 8][cix]     = f2tf(s[mf][nf][2]);
                Ps[r + 8][cix + 1] = f2tf(s[mf][nf][3]);
            }
        }
        __syncthreads();

        // O += P @ V  (k-dim = keys = 64)
        #pragma unroll
        for (int ks8 = 0; ks8 < 8; ks8++) {
            int k8 = ks8 << 3;
            uint32_t a[2][4], b[8][2];
            #pragma unroll
            for (int mf = 0; mf < 2; mf++) {
                int r = mb + (mf << 4) + grp;
                a[mf][0] = __float_as_uint(Ps[r][k8 + l4]);
                a[mf][1] = __float_as_uint(Ps[r + 8][k8 + l4]);
                a[mf][2] = __float_as_uint(Ps[r][k8 + l4 + 4]);
                a[mf][3] = __float_as_uint(Ps[r + 8][k8 + l4 + 4]);
            }
            #pragma unroll
            for (int df = 0; df < 8; df++) {
                int n = (df << 3) + grp;
                b[df][0] = __float_as_uint(Vs[k8 + l4][n]);
                b[df][1] = __float_as_uint(Vs[k8 + l4 + 4][n]);
            }
            #pragma unroll
            for (int mf = 0; mf < 2; mf++)
                #pragma unroll
                for (int df = 0; df < 8; df++)
                    mma8(o[mf][df], a[mf], b[df]);
        }
    }

    // epilogue: normalize + write out[b][n][h*64+d]
    int b = bh >> 4, h = bh & 15;
    #pragma unroll
    for (int mf = 0; mf < 2; mf++) {
        #pragma unroll
        for (int rr = 0; rr < 2; rr++) {
            int si = (mf << 1) + rr;
            float inv = 1.f / l_i[si];
            int n = (qt << 7) + mb + (mf << 4) + grp + (rr << 3);
            size_t base = ((size_t)(b * NN + n)) * CC + (h << 6);
            #pragma unroll
            for (int df = 0; df < 8; df++) {
                int col = (df << 3) + (l4 << 1);
                float2 vo = make_float2(o[mf][df][rr * 2] * inv,
                                        o[mf][df][rr * 2 + 1] * inv);
                *(float2*)&out[base + col] = vo;
            }
        }
    }
}

// ---------------------------------------------------------------------------
extern "C" void kernel_launch(void* const* d_in, const int* in_sizes, int n_in,
                              void* d_out, int out_size)
{
    const float* x1   = (const float*)d_in[0];
    const float* x2   = (const float*)d_in[1];
    const float* wq   = (const float*)d_in[2];
    const float* bq   = (const float*)d_in[3];
    const float* wkv  = (const float*)d_in[4];
    const float* bkv  = (const float*)d_in[5];
    const float* gmq  = (const float*)d_in[6];
    const float* btq  = (const float*)d_in[7];
    const float* gmk  = (const float*)d_in[8];
    const float* btk  = (const float*)d_in[9];
    float* out = (float*)d_out;

    const int ATTN_SMEM = (128 * 68 + 64 * 68 + 64 * 72 + 128 * 68) * 4;  // 105472
    cudaFuncSetAttribute(attn_kernel, cudaFuncAttributeMaxDynamicSharedMemorySize, ATTN_SMEM);

    dim3 pg(CC / 64, MM / 128);   // 16 x 64
    proj_kernel<<<pg, 128>>>(x1, wq,  bq,  CC,     0,  0);  // -> g_q
    proj_kernel<<<pg, 128>>>(x2, wkv, bkv, 2 * CC, 0,  1);  // -> g_k
    proj_kernel<<<pg, 128>>>(x2, wkv, bkv, 2 * CC, CC, 2);  // -> g_v

    ln_kernel<<<(2 * ROWS_PER) / 8, 256>>>(gmq, btq, gmk, btk);

    attn_kernel<<<dim3(NN / 128, BB * HH), 128, ATTN_SMEM>>>(out);
}

// round 4
// speedup vs baseline: 3.7191x; 1.5938x over previous
#include <cuda_runtime.h>
#include <cstdint>

#define BB 4
#define NN 2048
#define CC 1024
#define HH 16
#define DD 64
#define MM (BB*NN)          // 8192

// Scratch: q, k, v in [b*H+h][n][64] layout, stored tf32-rounded (post-LN for q,k)
__device__ float g_q[(size_t)MM * CC];
__device__ float g_k[(size_t)MM * CC];
__device__ float g_v[(size_t)MM * CC];

// ---------------------------------------------------------------------------
// helpers
// ---------------------------------------------------------------------------
__device__ __forceinline__ float f2tf(float x) {
    uint32_t u;
    asm("cvt.rna.tf32.f32 %0, %1;" : "=r"(u) : "f"(x));
    return __uint_as_float(u);
}

__device__ __forceinline__ uint32_t smem_u32(const void* p) {
    uint32_t a;
    asm("{ .reg .u64 t; cvta.to.shared.u64 t, %1; cvt.u32.u64 %0, t; }" : "=r"(a) : "l"(p));
    return a;
}

__device__ __forceinline__ void cp16(uint32_t dst, const void* src) {
    asm volatile("cp.async.cg.shared.global [%0], [%1], 16;" :: "r"(dst), "l"(src));
}
__device__ __forceinline__ void cp_commit() { asm volatile("cp.async.commit_group;"); }
__device__ __forceinline__ void cp_wait0()  { asm volatile("cp.async.wait_group 0;"); }

__device__ __forceinline__ void mma8(float c[4], const uint32_t a[4], const uint32_t b[2]) {
    asm volatile(
        "mma.sync.aligned.m16n8k8.row.col.f32.tf32.tf32.f32 "
        "{%0,%1,%2,%3}, {%4,%5,%6,%7}, {%8,%9}, {%0,%1,%2,%3};\n"
        : "+f"(c[0]), "+f"(c[1]), "+f"(c[2]), "+f"(c[3])
        : "r"(a[0]), "r"(a[1]), "r"(a[2]), "r"(a[3]), "r"(b[0]), "r"(b[1]));
}

// ---------------------------------------------------------------------------
// Projection GEMM (tf32 MMA) + fused bias + per-head LayerNorm + tf32 store.
// Block tile 128x64 (64 cols = one head), BK=32, 4 warps each 32rows x 64cols.
// Each output row lives in one 4-lane group -> LN reduction = 2 shfls.
// ---------------------------------------------------------------------------
__global__ __launch_bounds__(128) void proj_kernel(
    const float* __restrict__ A, const float* __restrict__ W,
    const float* __restrict__ bias, int ldb,
    const float* __restrict__ gamq, const float* __restrict__ betq,
    const float* __restrict__ gamk, const float* __restrict__ betk,
    int iskv)
{
    __shared__ float As[128][36];   // stride 36 ≡ 4 mod 32 -> conflict-free A frags
    __shared__ float Bs[32][72];    // stride 72 ≡ 8 mod 32 -> conflict-free B frags

    int tid  = threadIdx.x;
    int wid  = tid >> 5, lane = tid & 31;
    int grp  = lane >> 2, l4 = lane & 3;
    int m0   = blockIdx.y << 7;
    int col64 = blockIdx.x;          // q: 0..15, kv: 0..31
    int n0   = col64 << 6;

    // destination / LN config (uniform per block)
    float* Out; int head; int do_ln;
    const float* gam; const float* bet;
    if (!iskv)            { Out = g_q; head = col64;      do_ln = 1; gam = gamq; bet = betq; }
    else if (col64 < HH)  { Out = g_k; head = col64;      do_ln = 1; gam = gamk; bet = betk; }
    else                  { Out = g_v; head = col64 - HH; do_ln = 0; gam = gamq; bet = betq; }

    float c[2][8][4];
    #pragma unroll
    for (int mf = 0; mf < 2; mf++)
        #pragma unroll
        for (int nf = 0; nf < 8; nf++)
            #pragma unroll
            for (int i = 0; i < 4; i++) c[mf][nf][i] = 0.f;

    int ar = tid >> 3, ac = tid & 7;     // A loader: 16 rows/pass x 8 float4
    int br = tid >> 4, bc = tid & 15;    // B loader: 8 rows/pass x 16 float4
    const float* Ap = A + (size_t)(m0 + ar) * CC + (ac << 2);
    const float* Wp = W + (size_t)br * ldb + n0 + (bc << 2);

    for (int k0 = 0; k0 < CC; k0 += 32) {
        #pragma unroll
        for (int i = 0; i < 8; i++) {
            float4 v = *(const float4*)(Ap + (size_t)(i << 4) * CC + k0);
            float* d = &As[ar + (i << 4)][ac << 2];
            d[0] = f2tf(v.x); d[1] = f2tf(v.y); d[2] = f2tf(v.z); d[3] = f2tf(v.w);
        }
        #pragma unroll
        for (int i = 0; i < 4; i++) {
            float4 v = *(const float4*)(Wp + (size_t)(k0 + (i << 3)) * ldb);
            float* d = &Bs[br + (i << 3)][bc << 2];
            d[0] = f2tf(v.x); d[1] = f2tf(v.y); d[2] = f2tf(v.z); d[3] = f2tf(v.w);
        }
        __syncthreads();

        #pragma unroll
        for (int ks = 0; ks < 4; ks++) {
            int k8 = ks << 3;
            uint32_t a[2][4], b[8][2];
            #pragma unroll
            for (int mf = 0; mf < 2; mf++) {
                int r = (wid << 5) + (mf << 4) + grp;
                a[mf][0] = __float_as_uint(As[r][k8 + l4]);
                a[mf][1] = __float_as_uint(As[r + 8][k8 + l4]);
                a[mf][2] = __float_as_uint(As[r][k8 + l4 + 4]);
                a[mf][3] = __float_as_uint(As[r + 8][k8 + l4 + 4]);
            }
            #pragma unroll
            for (int nf = 0; nf < 8; nf++) {
                int n = (nf << 3) + grp;
                b[nf][0] = __float_as_uint(Bs[k8 + l4][n]);
                b[nf][1] = __float_as_uint(Bs[k8 + l4 + 4][n]);
            }
            #pragma unroll
            for (int mf = 0; mf < 2; mf++)
                #pragma unroll
                for (int nf = 0; nf < 8; nf++)
                    mma8(c[mf][nf], a[mf], b[nf]);
        }
        __syncthreads();
    }

    // Epilogue: bias + (optional) LayerNorm over the 64 cols of this head + tf32 store
    #pragma unroll
    for (int mf = 0; mf < 2; mf++) {
        float s0 = 0.f, s1 = 0.f, t0 = 0.f, t1 = 0.f;
        #pragma unroll
        for (int nf = 0; nf < 8; nf++) {
            int col = (nf << 3) + (l4 << 1);
            float b0 = bias[n0 + col], b1 = bias[n0 + col + 1];
            c[mf][nf][0] += b0; c[mf][nf][1] += b1;
            c[mf][nf][2] += b0; c[mf][nf][3] += b1;
            s0 += c[mf][nf][0] + c[mf][nf][1];
            s1 += c[mf][nf][2] + c[mf][nf][3];
            t0 += c[mf][nf][0] * c[mf][nf][0] + c[mf][nf][1] * c[mf][nf][1];
            t1 += c[mf][nf][2] * c[mf][nf][2] + c[mf][nf][3] * c[mf][nf][3];
        }
        #pragma unroll
        for (int off = 1; off <= 2; off <<= 1) {
            s0 += __shfl_xor_sync(0xffffffffu, s0, off);
            s1 += __shfl_xor_sync(0xffffffffu, s1, off);
            t0 += __shfl_xor_sync(0xffffffffu, t0, off);
            t1 += __shfl_xor_sync(0xffffffffu, t1, off);
        }
        float mean0 = 0.f, mean1 = 0.f, inv0 = 1.f, inv1 = 1.f;
        if (do_ln) {
            mean0 = s0 * 0.015625f;
            mean1 = s1 * 0.015625f;
            inv0 = rsqrtf(t0 * 0.015625f - mean0 * mean0 + 1e-5f);
            inv1 = rsqrtf(t1 * 0.015625f - mean1 * mean1 + 1e-5f);
        }

        int r0 = (wid << 5) + (mf << 4) + grp;
        int m = m0 + r0;
        int b = m >> 11, nseq = m & 2047;
        size_t base0 = (((size_t)(b * HH + head)) * NN + nseq) * DD;
        size_t base1 = base0 + (size_t)8 * DD;
        #pragma unroll
        for (int nf = 0; nf < 8; nf++) {
            int col = (nf << 3) + (l4 << 1);
            float y0 = c[mf][nf][0], y1 = c[mf][nf][1];
            float y2 = c[mf][nf][2], y3 = c[mf][nf][3];
            if (do_ln) {
                float g0 = gam[col], g1 = gam[col + 1];
                float e0 = bet[col], e1 = bet[col + 1];
                y0 = (y0 - mean0) * inv0 * g0 + e0;
                y1 = (y1 - mean0) * inv0 * g1 + e1;
                y2 = (y2 - mean1) * inv1 * g0 + e0;
                y3 = (y3 - mean1) * inv1 * g1 + e1;
            }
            *(float2*)&Out[base0 + col] = make_float2(f2tf(y0), f2tf(y1));
            *(float2*)&Out[base1 + col] = make_float2(f2tf(y2), f2tf(y3));
        }
    }
}

// ---------------------------------------------------------------------------
// Flash attention (tf32 MMA): 128-row Q tile/block, 4 warps (32 q-rows each),
// stream 64-row K/V tiles via cp.async; K[kt+1] prefetch overlaps P@V.
// Inputs already tf32-rounded. 105 KB smem -> 2 CTAs/SM.
// ---------------------------------------------------------------------------
__global__ __launch_bounds__(128) void attn_kernel(float* __restrict__ out)
{
    extern __shared__ float sm[];
    float (*Qs)[68] = (float(*)[68])sm;                                // 128x68
    float (*Ks)[68] = (float(*)[68])(sm + 128 * 68);                   // 64x68
    float (*Vs)[72] = (float(*)[72])(sm + 128 * 68 + 64 * 68);         // 64x72
    float (*Ps)[68] = (float(*)[68])(sm + 128 * 68 + 64 * 68 + 64 * 72); // 128x68

    int tid = threadIdx.x;
    int wid = tid >> 5, lane = tid & 31;
    int grp = lane >> 2, l4 = lane & 3;
    int bh = blockIdx.y, qt = blockIdx.x;
    int mb = wid << 5;

    const float* qb = g_q + (size_t)bh * (NN * 64) + (size_t)qt * (128 * 64);
    const float* kb = g_k + (size_t)bh * (NN * 64);
    const float* vb = g_v + (size_t)bh * (NN * 64);

    uint32_t qs_u = smem_u32(Qs), ks_u = smem_u32(Ks), vs_u = smem_u32(Vs);
    int lr = tid >> 4, lch = tid & 15;   // loader: row-of-16-chunks decomposition

    // prologue: async-load Q (128 rows), K0, V0 (64 rows each)
    #pragma unroll
    for (int i = 0; i < 8; i++) {
        int r = lr + (i << 3);
        cp16(qs_u + r * 272 + (lch << 4), qb + r * 64 + (lch << 2));
        cp16(qs_u + (r + 64) * 272 + (lch << 4), qb + (r + 64) * 64 + (lch << 2));
    }
    #pragma unroll
    for (int i = 0; i < 8; i++) {
        int r = lr + (i << 3);
        cp16(ks_u + r * 272 + (lch << 4), kb + r * 64 + (lch << 2));
        cp16(vs_u + r * 288 + (lch << 4), vb + r * 64 + (lch << 2));
    }
    cp_commit();
    cp_wait0();
    __syncthreads();

    float o[2][8][4];
    #pragma unroll
    for (int mf = 0; mf < 2; mf++)
        #pragma unroll
        for (int df = 0; df < 8; df++)
            #pragma unroll
            for (int i = 0; i < 4; i++) o[mf][df][i] = 0.f;
    float m_i[4] = {-1e30f, -1e30f, -1e30f, -1e30f};
    float l_i[4] = {0.f, 0.f, 0.f, 0.f};

    for (int kt = 0; kt < 32; kt++) {
        // S = Q @ K^T
        float s[2][8][4];
        #pragma unroll
        for (int mf = 0; mf < 2; mf++)
            #pragma unroll
            for (int nf = 0; nf < 8; nf++)
                #pragma unroll
                for (int i = 0; i < 4; i++) s[mf][nf][i] = 0.f;

        #pragma unroll
        for (int ks8 = 0; ks8 < 8; ks8++) {
            int k8 = ks8 << 3;
            uint32_t a[2][4], b[8][2];
            #pragma unroll
            for (int mf = 0; mf < 2; mf++) {
                int r = mb + (mf << 4) + grp;
                a[mf][0] = __float_as_uint(Qs[r][k8 + l4]);
                a[mf][1] = __float_as_uint(Qs[r + 8][k8 + l4]);
                a[mf][2] = __float_as_uint(Qs[r][k8 + l4 + 4]);
                a[mf][3] = __float_as_uint(Qs[r + 8][k8 + l4 + 4]);
            }
            #pragma unroll
            for (int nf = 0; nf < 8; nf++) {
                int n = (nf << 3) + grp;
                b[nf][0] = __float_as_uint(Ks[n][k8 + l4]);
                b[nf][1] = __float_as_uint(Ks[n][k8 + l4 + 4]);
            }
            #pragma unroll
            for (int mf = 0; mf < 2; mf++)
                #pragma unroll
                for (int nf = 0; nf < 8; nf++)
                    mma8(s[mf][nf], a[mf], b[nf]);
        }

        // online softmax (scale 1/8) + P write
        #pragma unroll
        for (int mf = 0; mf < 2; mf++) {
            #pragma unroll
            for (int nf = 0; nf < 8; nf++)
                #pragma unroll
                for (int i = 0; i < 4; i++) s[mf][nf][i] *= 0.125f;

            #pragma unroll
            for (int rr = 0; rr < 2; rr++) {
                int si = (mf << 1) + rr;
                float mx = -1e30f;
                #pragma unroll
                for (int nf = 0; nf < 8; nf++)
                    mx = fmaxf(mx, fmaxf(s[mf][nf][rr * 2], s[mf][nf][rr * 2 + 1]));
                mx = fmaxf(mx, __shfl_xor_sync(0xffffffffu, mx, 1));
                mx = fmaxf(mx, __shfl_xor_sync(0xffffffffu, mx, 2));
                float mn = fmaxf(m_i[si], mx);
                float alpha = __expf(m_i[si] - mn);
                float rs = 0.f;
                #pragma unroll
                for (int nf = 0; nf < 8; nf++) {
                    float p0 = __expf(s[mf][nf][rr * 2] - mn);
                    float p1 = __expf(s[mf][nf][rr * 2 + 1] - mn);
                    s[mf][nf][rr * 2] = p0; s[mf][nf][rr * 2 + 1] = p1;
                    rs += p0 + p1;
                }
                rs += __shfl_xor_sync(0xffffffffu, rs, 1);
                rs += __shfl_xor_sync(0xffffffffu, rs, 2);
                m_i[si] = mn;
                l_i[si] = l_i[si] * alpha + rs;
                #pragma unroll
                for (int df = 0; df < 8; df++) {
                    o[mf][df][rr * 2] *= alpha;
                    o[mf][df][rr * 2 + 1] *= alpha;
                }
            }
            int r = mb + (mf << 4) + grp;
            #pragma unroll
            for (int nf = 0; nf < 8; nf++) {
                int cix = (nf << 3) + (l4 << 1);
                Ps[r][cix]     = f2tf(s[mf][nf][0]);
                Ps[r][cix + 1] = f2tf(s[mf][nf][1]);
                Ps[r + 8][cix]     = f2tf(s[mf][nf][2]);
                Ps[r + 8][cix + 1] = f2tf(s[mf][nf][3]);
            }
        }
        __syncthreads();   // Ks reads done everywhere; Ps visible

        // prefetch K[kt+1] into Ks (overlaps with P@V below)
        if (kt < 31) {
            const float* kn = kb + (kt + 1) * 4096;
            #pragma unroll
            for (int i = 0; i < 8; i++) {
                int r = lr + (i << 3);
                cp16(ks_u + r * 272 + (lch << 4), kn + r * 64 + (lch << 2));
            }
            cp_commit();
        }

        // O += P @ V
        #pragma unroll
        for (int ks8 = 0; ks8 < 8; ks8++) {
            int k8 = ks8 << 3;
            uint32_t a[2][4], b[8][2];
            #pragma unroll
            for (int mf = 0; mf < 2; mf++) {
                int r = mb + (mf << 4) + grp;
                a[mf][0] = __float_as_uint(Ps[r][k8 + l4]);
                a[mf][1] = __float_as_uint(Ps[r + 8][k8 + l4]);
                a[mf][2] = __float_as_uint(Ps[r][k8 + l4 + 4]);
                a[mf][3] = __float_as_uint(Ps[r + 8][k8 + l4 + 4]);
            }
            #pragma unroll
            for (int df = 0; df < 8; df++) {
                int n = (df << 3) + grp;
                b[df][0] = __float_as_uint(Vs[k8 + l4][n]);
                b[df][1] = __float_as_uint(Vs[k8 + l4 + 4][n]);
            }
            #pragma unroll
            for (int mf = 0; mf < 2; mf++)
                #pragma unroll
                for (int df = 0; df < 8; df++)
                    mma8(o[mf][df], a[mf], b[df]);
        }
        __syncthreads();   // Vs reads done everywhere

        // load V[kt+1], wait both transfers, publish
        if (kt < 31) {
            const float* vn = vb + (kt + 1) * 4096;
            #pragma unroll
            for (int i = 0; i < 8; i++) {
                int r = lr + (i << 3);
                cp16(vs_u + r * 288 + (lch << 4), vn + r * 64 + (lch << 2));
            }
            cp_commit();
            cp_wait0();
            __syncthreads();
        }
    }

    // epilogue: normalize + write out[b][n][h*64+d]
    int b = bh >> 4, h = bh & 15;
    #pragma unroll
    for (int mf = 0; mf < 2; mf++) {
        #pragma unroll
        for (int rr = 0; rr < 2; rr++) {
            int si = (mf << 1) + rr;
            float inv = 1.f / l_i[si];
            int n = (qt << 7) + mb + (mf << 4) + grp + (rr << 3);
            size_t base = ((size_t)(b * NN + n)) * CC + (h << 6);
            #pragma unroll
            for (int df = 0; df < 8; df++) {
                int col = (df << 3) + (l4 << 1);
                float2 vo = make_float2(o[mf][df][rr * 2] * inv,
                                        o[mf][df][rr * 2 + 1] * inv);
                *(float2*)&out[base + col] = vo;
            }
        }
    }
}

// ---------------------------------------------------------------------------
extern "C" void kernel_launch(void* const* d_in, const int* in_sizes, int n_in,
                              void* d_out, int out_size)
{
    const float* x1   = (const float*)d_in[0];
    const float* x2   = (const float*)d_in[1];
    const float* wq   = (const float*)d_in[2];
    const float* bq   = (const float*)d_in[3];
    const float* wkv  = (const float*)d_in[4];
    const float* bkv  = (const float*)d_in[5];
    const float* gmq  = (const float*)d_in[6];
    const float* btq  = (const float*)d_in[7];
    const float* gmk  = (const float*)d_in[8];
    const float* btk  = (const float*)d_in[9];
    float* out = (float*)d_out;

    const int ATTN_SMEM = (128 * 68 + 64 * 68 + 64 * 72 + 128 * 68) * 4;  // 105472
    cudaFuncSetAttribute(attn_kernel, cudaFuncAttributeMaxDynamicSharedMemorySize, ATTN_SMEM);

    proj_kernel<<<dim3(CC / 64, MM / 128), 128>>>(x1, wq, bq, CC,
                                                  gmq, btq, gmk, btk, 0);
    proj_kernel<<<dim3(2 * CC / 64, MM / 128), 128>>>(x2, wkv, bkv, 2 * CC,
                                                      gmq, btq, gmk, btk, 1);

    attn_kernel<<<dim3(NN / 128, BB * HH), 128, ATTN_SMEM>>>(out);
}

// round 5
// speedup vs baseline: 3.9899x; 1.0728x over previous
#include <cuda_runtime.h>
#include <cstdint>

#define BB 4
#define NN 2048
#define CC 1024
#define HH 16
#define DD 64
#define MM (BB*NN)          // 8192

// Scratch: q, k, v in [b*H+h][n][64] layout, stored tf32-rounded (post-LN for q,k)
__device__ float g_q[(size_t)MM * CC];
__device__ float g_k[(size_t)MM * CC];
__device__ float g_v[(size_t)MM * CC];

// ---------------------------------------------------------------------------
// helpers
// ---------------------------------------------------------------------------
__device__ __forceinline__ float f2tf(float x) {
    uint32_t u;
    asm("cvt.rna.tf32.f32 %0, %1;" : "=r"(u) : "f"(x));
    return __uint_as_float(u);
}

__device__ __forceinline__ uint32_t smem_u32(const void* p) {
    uint32_t a;
    asm("{ .reg .u64 t; cvta.to.shared.u64 t, %1; cvt.u32.u64 %0, t; }" : "=r"(a) : "l"(p));
    return a;
}

__device__ __forceinline__ void cp16(uint32_t dst, const void* src) {
    asm volatile("cp.async.cg.shared.global [%0], [%1], 16;" :: "r"(dst), "l"(src));
}
__device__ __forceinline__ void cp_commit() { asm volatile("cp.async.commit_group;"); }
__device__ __forceinline__ void cp_wait0()  { asm volatile("cp.async.wait_group 0;"); }
__device__ __forceinline__ void cp_wait1()  { asm volatile("cp.async.wait_group 1;"); }

__device__ __forceinline__ void mma8(float c[4], const uint32_t a[4], const uint32_t b[2]) {
    asm volatile(
        "mma.sync.aligned.m16n8k8.row.col.f32.tf32.tf32.f32 "
        "{%0,%1,%2,%3}, {%4,%5,%6,%7}, {%8,%9}, {%0,%1,%2,%3};\n"
        : "+f"(c[0]), "+f"(c[1]), "+f"(c[2]), "+f"(c[3])
        : "r"(a[0]), "r"(a[1]), "r"(a[2]), "r"(a[3]), "r"(b[0]), "r"(b[1]));
}

// ---------------------------------------------------------------------------
// Fused projection GEMM (q + kv in one launch), tf32 MMA, register-staged
// double-buffered smem pipeline (1 barrier per 32-k chunk, LDG hidden by MMA).
// Block tile 128x64 (64 cols = one head), 4 warps each 32rows x 64cols.
// Epilogue: bias + per-head LayerNorm (q,k) + tf32 store.
// ---------------------------------------------------------------------------
#define PROJ_SMEM ((2*128*36 + 2*32*72) * 4)   // 55296 bytes

__global__ __launch_bounds__(128, 3) void proj_kernel(
    const float* __restrict__ x1, const float* __restrict__ wq, const float* __restrict__ bq,
    const float* __restrict__ x2, const float* __restrict__ wkv, const float* __restrict__ bkv,
    const float* __restrict__ gamq, const float* __restrict__ betq,
    const float* __restrict__ gamk, const float* __restrict__ betk)
{
    extern __shared__ float psm[];
    float (*As)[36] = (float(*)[36])psm;                  // [2*128][36], 36 ≡ 4 mod 32
    float (*Bs)[72] = (float(*)[72])(psm + 2 * 128 * 36); // [2*32][72],  72 ≡ 8 mod 32

    int tid  = threadIdx.x;
    int wid  = tid >> 5, lane = tid & 31;
    int grp  = lane >> 2, l4 = lane & 3;
    int m0   = blockIdx.y << 7;
    int cb   = blockIdx.x;            // 0..47

    const float *A, *W, *bias, *gam, *bet;
    float* Out; int ldb, n0, head, do_ln;
    if (cb < 16) {
        A = x1; W = wq; bias = bq; ldb = CC; n0 = cb << 6;
        Out = g_q; head = cb; do_ln = 1; gam = gamq; bet = betq;
    } else {
        int c2 = cb - 16;
        A = x2; W = wkv; bias = bkv; ldb = 2 * CC; n0 = c2 << 6;
        if (c2 < HH) { Out = g_k; head = c2;      do_ln = 1; gam = gamk; bet = betk; }
        else         { Out = g_v; head = c2 - HH; do_ln = 0; gam = gamq; bet = betq; }
    }

    float c[2][8][4];
    #pragma unroll
    for (int mf = 0; mf < 2; mf++)
        #pragma unroll
        for (int nf = 0; nf < 8; nf++)
            #pragma unroll
            for (int i = 0; i < 4; i++) c[mf][nf][i] = 0.f;

    int ar = tid >> 3, ac = tid & 7;     // A loader: 16 rows/pass x 8 float4
    int br = tid >> 4, bc = tid & 15;    // B loader: 8 rows/pass x 16 float4
    const float* Ap = A + (size_t)(m0 + ar) * CC + (ac << 2);
    const float* Wp = W + (size_t)br * ldb + n0 + (bc << 2);

    float4 av[8], bv[4];
    // tile 0 -> regs
    #pragma unroll
    for (int i = 0; i < 8; i++) av[i] = *(const float4*)(Ap + (size_t)(i << 4) * CC);
    #pragma unroll
    for (int i = 0; i < 4; i++) bv[i] = *(const float4*)(Wp + (size_t)(i << 3) * ldb);
    // store tile 0 -> buf0 (tf32-rounded)
    #pragma unroll
    for (int i = 0; i < 8; i++) {
        float* d = &As[ar + (i << 4)][ac << 2];
        d[0] = f2tf(av[i].x); d[1] = f2tf(av[i].y); d[2] = f2tf(av[i].z); d[3] = f2tf(av[i].w);
    }
    #pragma unroll
    for (int i = 0; i < 4; i++) {
        float* d = &Bs[br + (i << 3)][bc << 2];
        d[0] = f2tf(bv[i].x); d[1] = f2tf(bv[i].y); d[2] = f2tf(bv[i].z); d[3] = f2tf(bv[i].w);
    }

    for (int ch = 0; ch < 32; ch++) {
        int buf = ch & 1;
        __syncthreads();
        // issue LDG for chunk ch+1 (hidden behind MMAs below)
        if (ch < 31) {
            int k0 = (ch + 1) << 5;
            #pragma unroll
            for (int i = 0; i < 8; i++)
                av[i] = *(const float4*)(Ap + (size_t)(i << 4) * CC + k0);
            #pragma unroll
            for (int i = 0; i < 4; i++)
                bv[i] = *(const float4*)(Wp + (size_t)(k0 + (i << 3)) * ldb);
        }

        float (*Ab)[36] = &As[buf << 7];
        float (*Bb)[72] = &Bs[buf << 5];
        #pragma unroll
        for (int ks = 0; ks < 4; ks++) {
            int k8 = ks << 3;
            uint32_t a[2][4], b[8][2];
            #pragma unroll
            for (int mf = 0; mf < 2; mf++) {
                int r = (wid << 5) + (mf << 4) + grp;
                a[mf][0] = __float_as_uint(Ab[r][k8 + l4]);
                a[mf][1] = __float_as_uint(Ab[r + 8][k8 + l4]);
                a[mf][2] = __float_as_uint(Ab[r][k8 + l4 + 4]);
                a[mf][3] = __float_as_uint(Ab[r + 8][k8 + l4 + 4]);
            }
            #pragma unroll
            for (int nf = 0; nf < 8; nf++) {
                int n = (nf << 3) + grp;
                b[nf][0] = __float_as_uint(Bb[k8 + l4][n]);
                b[nf][1] = __float_as_uint(Bb[k8 + l4 + 4][n]);
            }
            #pragma unroll
            for (int mf = 0; mf < 2; mf++)
                #pragma unroll
                for (int nf = 0; nf < 8; nf++)
                    mma8(c[mf][nf], a[mf], b[nf]);
        }

        // store prefetched tile into the other buffer
        if (ch < 31) {
            int ob = buf ^ 1;
            #pragma unroll
            for (int i = 0; i < 8; i++) {
                float* d = &As[(ob << 7) + ar + (i << 4)][ac << 2];
                d[0] = f2tf(av[i].x); d[1] = f2tf(av[i].y); d[2] = f2tf(av[i].z); d[3] = f2tf(av[i].w);
            }
            #pragma unroll
            for (int i = 0; i < 4; i++) {
                float* d = &Bs[(ob << 5) + br + (i << 3)][bc << 2];
                d[0] = f2tf(bv[i].x); d[1] = f2tf(bv[i].y); d[2] = f2tf(bv[i].z); d[3] = f2tf(bv[i].w);
            }
        }
    }

    // Epilogue: bias + (optional) LayerNorm over the 64 cols of this head + tf32 store
    #pragma unroll
    for (int mf = 0; mf < 2; mf++) {
        float s0 = 0.f, s1 = 0.f, t0 = 0.f, t1 = 0.f;
        #pragma unroll
        for (int nf = 0; nf < 8; nf++) {
            int col = (nf << 3) + (l4 << 1);
            float b0 = bias[n0 + col], b1 = bias[n0 + col + 1];
            c[mf][nf][0] += b0; c[mf][nf][1] += b1;
            c[mf][nf][2] += b0; c[mf][nf][3] += b1;
            s0 += c[mf][nf][0] + c[mf][nf][1];
            s1 += c[mf][nf][2] + c[mf][nf][3];
            t0 += c[mf][nf][0] * c[mf][nf][0] + c[mf][nf][1] * c[mf][nf][1];
            t1 += c[mf][nf][2] * c[mf][nf][2] + c[mf][nf][3] * c[mf][nf][3];
        }
        #pragma unroll
        for (int off = 1; off <= 2; off <<= 1) {
            s0 += __shfl_xor_sync(0xffffffffu, s0, off);
            s1 += __shfl_xor_sync(0xffffffffu, s1, off);
            t0 += __shfl_xor_sync(0xffffffffu, t0, off);
            t1 += __shfl_xor_sync(0xffffffffu, t1, off);
        }
        float mean0 = 0.f, mean1 = 0.f, inv0 = 1.f, inv1 = 1.f;
        if (do_ln) {
            mean0 = s0 * 0.015625f;
            mean1 = s1 * 0.015625f;
            inv0 = rsqrtf(t0 * 0.015625f - mean0 * mean0 + 1e-5f);
            inv1 = rsqrtf(t1 * 0.015625f - mean1 * mean1 + 1e-5f);
        }

        int r0 = (wid << 5) + (mf << 4) + grp;
        int m = m0 + r0;
        int b = m >> 11, nseq = m & 2047;
        size_t base0 = (((size_t)(b * HH + head)) * NN + nseq) * DD;
        size_t base1 = base0 + (size_t)8 * DD;
        #pragma unroll
        for (int nf = 0; nf < 8; nf++) {
            int col = (nf << 3) + (l4 << 1);
            float y0 = c[mf][nf][0], y1 = c[mf][nf][1];
            float y2 = c[mf][nf][2], y3 = c[mf][nf][3];
            if (do_ln) {
                float g0 = gam[col], g1 = gam[col + 1];
                float e0 = bet[col], e1 = bet[col + 1];
                y0 = (y0 - mean0) * inv0 * g0 + e0;
                y1 = (y1 - mean0) * inv0 * g1 + e1;
                y2 = (y2 - mean1) * inv1 * g0 + e0;
                y3 = (y3 - mean1) * inv1 * g1 + e1;
            }
            *(float2*)&Out[base0 + col] = make_float2(f2tf(y0), f2tf(y1));
            *(float2*)&Out[base1 + col] = make_float2(f2tf(y2), f2tf(y3));
        }
    }
}

// ---------------------------------------------------------------------------
// Flash attention (tf32 MMA): 128-row Q tile/block, 4 warps (32 q-rows each),
// stream 64-row K/V tiles via cp.async. Pipeline: K[kt+1] flies during PV,
// V[kt+1] flies during next S+softmax. 105 KB smem -> 2 CTAs/SM.
// ---------------------------------------------------------------------------
__global__ __launch_bounds__(128) void attn_kernel(float* __restrict__ out)
{
    extern __shared__ float sm[];
    float (*Qs)[68] = (float(*)[68])sm;                                // 128x68
    float (*Ks)[68] = (float(*)[68])(sm + 128 * 68);                   // 64x68
    float (*Vs)[72] = (float(*)[72])(sm + 128 * 68 + 64 * 68);         // 64x72
    float (*Ps)[68] = (float(*)[68])(sm + 128 * 68 + 64 * 68 + 64 * 72); // 128x68

    int tid = threadIdx.x;
    int wid = tid >> 5, lane = tid & 31;
    int grp = lane >> 2, l4 = lane & 3;
    int bh = blockIdx.y, qt = blockIdx.x;
    int mb = wid << 5;

    const float* qb = g_q + (size_t)bh * (NN * 64) + (size_t)qt * (128 * 64);
    const float* kb = g_k + (size_t)bh * (NN * 64);
    const float* vb = g_v + (size_t)bh * (NN * 64);

    uint32_t qs_u = smem_u32(Qs), ks_u = smem_u32(Ks), vs_u = smem_u32(Vs);
    int lr = tid >> 4, lch = tid & 15;   // loader decomposition

    // prologue: async-load Q (128 rows), K0, V0 (64 rows each)
    #pragma unroll
    for (int i = 0; i < 8; i++) {
        int r = lr + (i << 3);
        cp16(qs_u + r * 272 + (lch << 4), qb + r * 64 + (lch << 2));
        cp16(qs_u + (r + 64) * 272 + (lch << 4), qb + (r + 64) * 64 + (lch << 2));
    }
    #pragma unroll
    for (int i = 0; i < 8; i++) {
        int r = lr + (i << 3);
        cp16(ks_u + r * 272 + (lch << 4), kb + r * 64 + (lch << 2));
        cp16(vs_u + r * 288 + (lch << 4), vb + r * 64 + (lch << 2));
    }
    cp_commit();
    cp_wait0();
    __syncthreads();

    float o[2][8][4];
    #pragma unroll
    for (int mf = 0; mf < 2; mf++)
        #pragma unroll
        for (int df = 0; df < 8; df++)
            #pragma unroll
            for (int i = 0; i < 4; i++) o[mf][df][i] = 0.f;
    float m_i[4] = {-1e30f, -1e30f, -1e30f, -1e30f};
    float l_i[4] = {0.f, 0.f, 0.f, 0.f};

    for (int kt = 0; kt < 32; kt++) {
        // S = Q @ K^T  (Ks valid: waited at end of previous iter / prologue)
        float s[2][8][4];
        #pragma unroll
        for (int mf = 0; mf < 2; mf++)
            #pragma unroll
            for (int nf = 0; nf < 8; nf++)
                #pragma unroll
                for (int i = 0; i < 4; i++) s[mf][nf][i] = 0.f;

        #pragma unroll
        for (int ks8 = 0; ks8 < 8; ks8++) {
            int k8 = ks8 << 3;
            uint32_t a[2][4], b[8][2];
            #pragma unroll
            for (int mf = 0; mf < 2; mf++) {
                int r = mb + (mf << 4) + grp;
                a[mf][0] = __float_as_uint(Qs[r][k8 + l4]);
                a[mf][1] = __float_as_uint(Qs[r + 8][k8 + l4]);
                a[mf][2] = __float_as_uint(Qs[r][k8 + l4 + 4]);
                a[mf][3] = __float_as_uint(Qs[r + 8][k8 + l4 + 4]);
            }
            #pragma unroll
            for (int nf = 0; nf < 8; nf++) {
                int n = (nf << 3) + grp;
                b[nf][0] = __float_as_uint(Ks[n][k8 + l4]);
                b[nf][1] = __float_as_uint(Ks[n][k8 + l4 + 4]);
            }
            #pragma unroll
            for (int mf = 0; mf < 2; mf++)
                #pragma unroll
                for (int nf = 0; nf < 8; nf++)
                    mma8(s[mf][nf], a[mf], b[nf]);
        }

        // online softmax (scale 1/8) + P write
        #pragma unroll
        for (int mf = 0; mf < 2; mf++) {
            #pragma unroll
            for (int nf = 0; nf < 8; nf++)
                #pragma unroll
                for (int i = 0; i < 4; i++) s[mf][nf][i] *= 0.125f;

            #pragma unroll
            for (int rr = 0; rr < 2; rr++) {
                int si = (mf << 1) + rr;
                float mx = -1e30f;
                #pragma unroll
                for (int nf = 0; nf < 8; nf++)
                    mx = fmaxf(mx, fmaxf(s[mf][nf][rr * 2], s[mf][nf][rr * 2 + 1]));
                mx = fmaxf(mx, __shfl_xor_sync(0xffffffffu, mx, 1));
                mx = fmaxf(mx, __shfl_xor_sync(0xffffffffu, mx, 2));
                float mn = fmaxf(m_i[si], mx);
                float alpha = __expf(m_i[si] - mn);
                float rs = 0.f;
                #pragma unroll
                for (int nf = 0; nf < 8; nf++) {
                    float p0 = __expf(s[mf][nf][rr * 2] - mn);
                    float p1 = __expf(s[mf][nf][rr * 2 + 1] - mn);
                    s[mf][nf][rr * 2] = p0; s[mf][nf][rr * 2 + 1] = p1;
                    rs += p0 + p1;
                }
                rs += __shfl_xor_sync(0xffffffffu, rs, 1);
                rs += __shfl_xor_sync(0xffffffffu, rs, 2);
                m_i[si] = mn;
                l_i[si] = l_i[si] * alpha + rs;
                #pragma unroll
                for (int df = 0; df < 8; df++) {
                    o[mf][df][rr * 2] *= alpha;
                    o[mf][df][rr * 2 + 1] *= alpha;
                }
            }
            int r = mb + (mf << 4) + grp;
            #pragma unroll
            for (int nf = 0; nf < 8; nf++) {
                int cix = (nf << 3) + (l4 << 1);
                Ps[r][cix]     = f2tf(s[mf][nf][0]);
                Ps[r][cix + 1] = f2tf(s[mf][nf][1]);
                Ps[r + 8][cix]     = f2tf(s[mf][nf][2]);
                Ps[r + 8][cix + 1] = f2tf(s[mf][nf][3]);
            }
        }
        __syncthreads();   // Ks dead everywhere; Ps visible

        // issue K[kt+1] -> Ks (flies through V-wait + PV)
        if (kt < 31) {
            const float* kn = kb + (kt + 1) * 4096;
            #pragma unroll
            for (int i = 0; i < 8; i++) {
                int r = lr + (i << 3);
                cp16(ks_u + r * 272 + (lch << 4), kn + r * 64 + (lch << 2));
            }
            cp_commit();
            cp_wait1();    // drains V[kt] (issued last iter); K[kt+1] stays in flight
        } else {
            cp_wait0();    // drain V[31]
        }
        __syncthreads();   // V[kt] visible to all

        // O += P @ V
        #pragma unroll
        for (int ks8 = 0; ks8 < 8; ks8++) {
            int k8 = ks8 << 3;
            uint32_t a[2][4], b[8][2];
            #pragma unroll
            for (int mf = 0; mf < 2; mf++) {
                int r = mb + (mf << 4) + grp;
                a[mf][0] = __float_as_uint(Ps[r][k8 + l4]);
                a[mf][1] = __float_as_uint(Ps[r + 8][k8 + l4]);
                a[mf][2] = __float_as_uint(Ps[r][k8 + l4 + 4]);
                a[mf][3] = __float_as_uint(Ps[r + 8][k8 + l4 + 4]);
            }
            #pragma unroll
            for (int df = 0; df < 8; df++) {
                int n = (df << 3) + grp;
                b[df][0] = __float_as_uint(Vs[k8 + l4][n]);
                b[df][1] = __float_as_uint(Vs[k8 + l4 + 4][n]);
            }
            #pragma unroll
            for (int mf = 0; mf < 2; mf++)
                #pragma unroll
                for (int df = 0; df < 8; df++)
                    mma8(o[mf][df], a[mf], b[df]);
        }

        if (kt < 31) {
            __syncthreads();   // Vs dead everywhere
            // issue V[kt+1] -> Vs (flies through next S + softmax)
            const float* vn = vb + (kt + 1) * 4096;
            #pragma unroll
            for (int i = 0; i < 8; i++) {
                int r = lr + (i << 3);
                cp16(vs_u + r * 288 + (lch << 4), vn + r * 64 + (lch << 2));
            }
            cp_commit();
            cp_wait1();        // drains K[kt+1]; V[kt+1] stays in flight
            __syncthreads();   // K[kt+1] visible -> next S may read Ks
        }
    }

    // epilogue: normalize + write out[b][n][h*64+d]
    int b = bh >> 4, h = bh & 15;
    #pragma unroll
    for (int mf = 0; mf < 2; mf++) {
        #pragma unroll
        for (int rr = 0; rr < 2; rr++) {
            int si = (mf << 1) + rr;
            float inv = 1.f / l_i[si];
            int n = (qt << 7) + mb + (mf << 4) + grp + (rr << 3);
            size_t base = ((size_t)(b * NN + n)) * CC + (h << 6);
            #pragma unroll
            for (int df = 0; df < 8; df++) {
                int col = (df << 3) + (l4 << 1);
                float2 vo = make_float2(o[mf][df][rr * 2] * inv,
                                        o[mf][df][rr * 2 + 1] * inv);
                *(float2*)&out[base + col] = vo;
            }
        }
    }
}

// ---------------------------------------------------------------------------
extern "C" void kernel_launch(void* const* d_in, const int* in_sizes, int n_in,
                              void* d_out, int out_size)
{
    const float* x1   = (const float*)d_in[0];
    const float* x2   = (const float*)d_in[1];
    const float* wq   = (const float*)d_in[2];
    const float* bq   = (const float*)d_in[3];
    const float* wkv  = (const float*)d_in[4];
    const float* bkv  = (const float*)d_in[5];
    const float* gmq  = (const float*)d_in[6];
    const float* btq  = (const float*)d_in[7];
    const float* gmk  = (const float*)d_in[8];
    const float* btk  = (const float*)d_in[9];
    float* out = (float*)d_out;

    const int ATTN_SMEM = (128 * 68 + 64 * 68 + 64 * 72 + 128 * 68) * 4;  // 105472
    cudaFuncSetAttribute(attn_kernel, cudaFuncAttributeMaxDynamicSharedMemorySize, ATTN_SMEM);
    cudaFuncSetAttribute(proj_kernel, cudaFuncAttributeMaxDynamicSharedMemorySize, PROJ_SMEM);

    proj_kernel<<<dim3(48, MM / 128), 128, PROJ_SMEM>>>(
        x1, wq, bq, x2, wkv, bkv, gmq, btq, gmk, btk);

    attn_kernel<<<dim3(NN / 128, BB * HH), 128, ATTN_SMEM>>>(out);
}

// round 6
// speedup vs baseline: 4.2501x; 1.0652x over previous
#include <cuda_runtime.h>
#include <cstdint>

#define BB 4
#define NN 2048
#define CC 1024
#define HH 16
#define DD 64
#define MM (BB*NN)          // 8192

// Scratch: q, k, v in [b*H+h][n][64] layout, stored tf32-rounded (post-LN for q,k)
// q additionally pre-scaled by 0.125*log2(e) so attention scores are in log2 domain.
__device__ float g_q[(size_t)MM * CC];
__device__ float g_k[(size_t)MM * CC];
__device__ float g_v[(size_t)MM * CC];

// ---------------------------------------------------------------------------
// helpers
// ---------------------------------------------------------------------------
__device__ __forceinline__ float f2tf(float x) {
    uint32_t u;
    asm("cvt.rna.tf32.f32 %0, %1;" : "=r"(u) : "f"(x));
    return __uint_as_float(u);
}

__device__ __forceinline__ float ex2(float x) {
    float r;
    asm("ex2.approx.ftz.f32 %0, %1;" : "=f"(r) : "f"(x));
    return r;
}

__device__ __forceinline__ uint32_t smem_u32(const void* p) {
    uint32_t a;
    asm("{ .reg .u64 t; cvta.to.shared.u64 t, %1; cvt.u32.u64 %0, t; }" : "=r"(a) : "l"(p));
    return a;
}

__device__ __forceinline__ void cp16(uint32_t dst, const void* src) {
    asm volatile("cp.async.cg.shared.global [%0], [%1], 16;" :: "r"(dst), "l"(src));
}
__device__ __forceinline__ void cp_commit() { asm volatile("cp.async.commit_group;"); }
__device__ __forceinline__ void cp_wait0()  { asm volatile("cp.async.wait_group 0;"); }
__device__ __forceinline__ void cp_wait1()  { asm volatile("cp.async.wait_group 1;"); }

__device__ __forceinline__ void mma8(float c[4], const uint32_t a[4], const uint32_t b[2]) {
    asm volatile(
        "mma.sync.aligned.m16n8k8.row.col.f32.tf32.tf32.f32 "
        "{%0,%1,%2,%3}, {%4,%5,%6,%7}, {%8,%9}, {%0,%1,%2,%3};\n"
        : "+f"(c[0]), "+f"(c[1]), "+f"(c[2]), "+f"(c[3])
        : "r"(a[0]), "r"(a[1]), "r"(a[2]), "r"(a[3]), "r"(b[0]), "r"(b[1]));
}

// ---------------------------------------------------------------------------
// Fused projection GEMM (q + kv in one launch), tf32 MMA, register-staged
// double-buffered smem pipeline. Block tile 128x64 (64 cols = one head),
// 4 warps each 32rows x 64cols. Epilogue: bias + per-head LayerNorm (q,k),
// q scaled by 0.125*log2(e), tf32 store.
// ---------------------------------------------------------------------------
#define PROJ_SMEM ((2*128*36 + 2*32*72) * 4)   // 55296 bytes

__global__ __launch_bounds__(128, 3) void proj_kernel(
    const float* __restrict__ x1, const float* __restrict__ wq, const float* __restrict__ bq,
    const float* __restrict__ x2, const float* __restrict__ wkv, const float* __restrict__ bkv,
    const float* __restrict__ gamq, const float* __restrict__ betq,
    const float* __restrict__ gamk, const float* __restrict__ betk)
{
    extern __shared__ float psm[];
    float (*As)[36] = (float(*)[36])psm;                  // [2*128][36], 36 ≡ 4 mod 32
    float (*Bs)[72] = (float(*)[72])(psm + 2 * 128 * 36); // [2*32][72],  72 ≡ 8 mod 32

    int tid  = threadIdx.x;
    int wid  = tid >> 5, lane = tid & 31;
    int grp  = lane >> 2, l4 = lane & 3;
    int m0   = blockIdx.y << 7;
    int cb   = blockIdx.x;            // 0..47

    const float *A, *W, *bias, *gam, *bet;
    float* Out; int ldb, n0, head, do_ln, is_q;
    if (cb < 16) {
        A = x1; W = wq; bias = bq; ldb = CC; n0 = cb << 6;
        Out = g_q; head = cb; do_ln = 1; is_q = 1; gam = gamq; bet = betq;
    } else {
        int c2 = cb - 16;
        A = x2; W = wkv; bias = bkv; ldb = 2 * CC; n0 = c2 << 6; is_q = 0;
        if (c2 < HH) { Out = g_k; head = c2;      do_ln = 1; gam = gamk; bet = betk; }
        else         { Out = g_v; head = c2 - HH; do_ln = 0; gam = gamq; bet = betq; }
    }

    float c[2][8][4];
    #pragma unroll
    for (int mf = 0; mf < 2; mf++)
        #pragma unroll
        for (int nf = 0; nf < 8; nf++)
            #pragma unroll
            for (int i = 0; i < 4; i++) c[mf][nf][i] = 0.f;

    int ar = tid >> 3, ac = tid & 7;
    int br = tid >> 4, bc = tid & 15;
    const float* Ap = A + (size_t)(m0 + ar) * CC + (ac << 2);
    const float* Wp = W + (size_t)br * ldb + n0 + (bc << 2);

    float4 av[8], bv[4];
    #pragma unroll
    for (int i = 0; i < 8; i++) av[i] = *(const float4*)(Ap + (size_t)(i << 4) * CC);
    #pragma unroll
    for (int i = 0; i < 4; i++) bv[i] = *(const float4*)(Wp + (size_t)(i << 3) * ldb);
    #pragma unroll
    for (int i = 0; i < 8; i++) {
        float* d = &As[ar + (i << 4)][ac << 2];
        d[0] = f2tf(av[i].x); d[1] = f2tf(av[i].y); d[2] = f2tf(av[i].z); d[3] = f2tf(av[i].w);
    }
    #pragma unroll
    for (int i = 0; i < 4; i++) {
        float* d = &Bs[br + (i << 3)][bc << 2];
        d[0] = f2tf(bv[i].x); d[1] = f2tf(bv[i].y); d[2] = f2tf(bv[i].z); d[3] = f2tf(bv[i].w);
    }

    for (int ch = 0; ch < 32; ch++) {
        int buf = ch & 1;
        __syncthreads();
        if (ch < 31) {
            int k0 = (ch + 1) << 5;
            #pragma unroll
            for (int i = 0; i < 8; i++)
                av[i] = *(const float4*)(Ap + (size_t)(i << 4) * CC + k0);
            #pragma unroll
            for (int i = 0; i < 4; i++)
                bv[i] = *(const float4*)(Wp + (size_t)(k0 + (i << 3)) * ldb);
        }

        float (*Ab)[36] = &As[buf << 7];
        float (*Bb)[72] = &Bs[buf << 5];
        #pragma unroll
        for (int ks = 0; ks < 4; ks++) {
            int k8 = ks << 3;
            uint32_t a[2][4], b[8][2];
            #pragma unroll
            for (int mf = 0; mf < 2; mf++) {
                int r = (wid << 5) + (mf << 4) + grp;
                a[mf][0] = __float_as_uint(Ab[r][k8 + l4]);
                a[mf][1] = __float_as_uint(Ab[r + 8][k8 + l4]);
                a[mf][2] = __float_as_uint(Ab[r][k8 + l4 + 4]);
                a[mf][3] = __float_as_uint(Ab[r + 8][k8 + l4 + 4]);
            }
            #pragma unroll
            for (int nf = 0; nf < 8; nf++) {
                int n = (nf << 3) + grp;
                b[nf][0] = __float_as_uint(Bb[k8 + l4][n]);
                b[nf][1] = __float_as_uint(Bb[k8 + l4 + 4][n]);
            }
            #pragma unroll
            for (int mf = 0; mf < 2; mf++)
                #pragma unroll
                for (int nf = 0; nf < 8; nf++)
                    mma8(c[mf][nf], a[mf], b[nf]);
        }

        if (ch < 31) {
            int ob = buf ^ 1;
            #pragma unroll
            for (int i = 0; i < 8; i++) {
                float* d = &As[(ob << 7) + ar + (i << 4)][ac << 2];
                d[0] = f2tf(av[i].x); d[1] = f2tf(av[i].y); d[2] = f2tf(av[i].z); d[3] = f2tf(av[i].w);
            }
            #pragma unroll
            for (int i = 0; i < 4; i++) {
                float* d = &Bs[(ob << 5) + br + (i << 3)][bc << 2];
                d[0] = f2tf(bv[i].x); d[1] = f2tf(bv[i].y); d[2] = f2tf(bv[i].z); d[3] = f2tf(bv[i].w);
            }
        }
    }

    // Epilogue: bias + (optional) LayerNorm + (q) log2-domain scale + tf32 store
    const float SC = 0.18033688011112042f;   // 0.125 * log2(e)
    #pragma unroll
    for (int mf = 0; mf < 2; mf++) {
        float s0 = 0.f, s1 = 0.f, t0 = 0.f, t1 = 0.f;
        #pragma unroll
        for (int nf = 0; nf < 8; nf++) {
            int col = (nf << 3) + (l4 << 1);
            float b0 = bias[n0 + col], b1 = bias[n0 + col + 1];
            c[mf][nf][0] += b0; c[mf][nf][1] += b1;
            c[mf][nf][2] += b0; c[mf][nf][3] += b1;
            s0 += c[mf][nf][0] + c[mf][nf][1];
            s1 += c[mf][nf][2] + c[mf][nf][3];
            t0 += c[mf][nf][0] * c[mf][nf][0] + c[mf][nf][1] * c[mf][nf][1];
            t1 += c[mf][nf][2] * c[mf][nf][2] + c[mf][nf][3] * c[mf][nf][3];
        }
        #pragma unroll
        for (int off = 1; off <= 2; off <<= 1) {
            s0 += __shfl_xor_sync(0xffffffffu, s0, off);
            s1 += __shfl_xor_sync(0xffffffffu, s1, off);
            t0 += __shfl_xor_sync(0xffffffffu, t0, off);
            t1 += __shfl_xor_sync(0xffffffffu, t1, off);
        }
        float mean0 = 0.f, mean1 = 0.f, inv0 = 1.f, inv1 = 1.f;
        if (do_ln) {
            mean0 = s0 * 0.015625f;
            mean1 = s1 * 0.015625f;
            inv0 = rsqrtf(t0 * 0.015625f - mean0 * mean0 + 1e-5f);
            inv1 = rsqrtf(t1 * 0.015625f - mean1 * mean1 + 1e-5f);
        }

        int r0 = (wid << 5) + (mf << 4) + grp;
        int m = m0 + r0;
        int b = m >> 11, nseq = m & 2047;
        size_t base0 = (((size_t)(b * HH + head)) * NN + nseq) * DD;
        size_t base1 = base0 + (size_t)8 * DD;
        #pragma unroll
        for (int nf = 0; nf < 8; nf++) {
            int col = (nf << 3) + (l4 << 1);
            float y0 = c[mf][nf][0], y1 = c[mf][nf][1];
            float y2 = c[mf][nf][2], y3 = c[mf][nf][3];
            if (do_ln) {
                float g0 = gam[col], g1 = gam[col + 1];
                float e0 = bet[col], e1 = bet[col + 1];
                y0 = (y0 - mean0) * inv0 * g0 + e0;
                y1 = (y1 - mean0) * inv0 * g1 + e1;
                y2 = (y2 - mean1) * inv1 * g0 + e0;
                y3 = (y3 - mean1) * inv1 * g1 + e1;
            }
            if (is_q) { y0 *= SC; y1 *= SC; y2 *= SC; y3 *= SC; }
            *(float2*)&Out[base0 + col] = make_float2(f2tf(y0), f2tf(y1));
            *(float2*)&Out[base1 + col] = make_float2(f2tf(y2), f2tf(y3));
        }
    }
}

// ---------------------------------------------------------------------------
// Flash attention (tf32 MMA): 128-row Q tile/block, 4 warps (32 q-rows each),
// stream 64-row K/V tiles via cp.async. P kept in registers: S-fragment ->
// A-fragment conversion via intra-quad shuffles (no Ps smem, no round trip).
// 69 KB smem -> 2+ CTAs/SM.
// ---------------------------------------------------------------------------
#define ATTN_SMEM ((128*68 + 64*68 + 64*72) * 4)   // 70656 bytes

__global__ __launch_bounds__(128, 2) void attn_kernel(float* __restrict__ out)
{
    extern __shared__ float sm[];
    float (*Qs)[68] = (float(*)[68])sm;                        // 128x68
    float (*Ks)[68] = (float(*)[68])(sm + 128 * 68);           // 64x68
    float (*Vs)[72] = (float(*)[72])(sm + 128 * 68 + 64 * 68); // 64x72

    int tid = threadIdx.x;
    int wid = tid >> 5, lane = tid & 31;
    int grp = lane >> 2, l4 = lane & 3;
    int bh = blockIdx.y, qt = blockIdx.x;
    int mb = wid << 5;

    const float* qb = g_q + (size_t)bh * (NN * 64) + (size_t)qt * (128 * 64);
    const float* kb = g_k + (size_t)bh * (NN * 64);
    const float* vb = g_v + (size_t)bh * (NN * 64);

    uint32_t qs_u = smem_u32(Qs), ks_u = smem_u32(Ks), vs_u = smem_u32(Vs);
    int lr = tid >> 4, lch = tid & 15;

    // prologue: async-load Q (128 rows), K0, V0 (64 rows each), one group
    #pragma unroll
    for (int i = 0; i < 8; i++) {
        int r = lr + (i << 3);
        cp16(qs_u + r * 272 + (lch << 4), qb + r * 64 + (lch << 2));
        cp16(qs_u + (r + 64) * 272 + (lch << 4), qb + (r + 64) * 64 + (lch << 2));
        cp16(ks_u + r * 272 + (lch << 4), kb + r * 64 + (lch << 2));
        cp16(vs_u + r * 288 + (lch << 4), vb + r * 64 + (lch << 2));
    }
    cp_commit();
    cp_wait0();
    __syncthreads();

    float o[2][8][4];
    #pragma unroll
    for (int mf = 0; mf < 2; mf++)
        #pragma unroll
        for (int df = 0; df < 8; df++)
            #pragma unroll
            for (int i = 0; i < 4; i++) o[mf][df][i] = 0.f;
    float m_i[4] = {-1e30f, -1e30f, -1e30f, -1e30f};
    float l_i[4] = {0.f, 0.f, 0.f, 0.f};

    for (int kt = 0; kt < 32; kt++) {
        // S = Q @ K^T  (scores arrive already in log2 domain: q pre-scaled)
        float s[2][8][4];
        #pragma unroll
        for (int mf = 0; mf < 2; mf++)
            #pragma unroll
            for (int nf = 0; nf < 8; nf++)
                #pragma unroll
                for (int i = 0; i < 4; i++) s[mf][nf][i] = 0.f;

        #pragma unroll
        for (int ks8 = 0; ks8 < 8; ks8++) {
            int k8 = ks8 << 3;
            uint32_t a[2][4], b[8][2];
            #pragma unroll
            for (int mf = 0; mf < 2; mf++) {
                int r = mb + (mf << 4) + grp;
                a[mf][0] = __float_as_uint(Qs[r][k8 + l4]);
                a[mf][1] = __float_as_uint(Qs[r + 8][k8 + l4]);
                a[mf][2] = __float_as_uint(Qs[r][k8 + l4 + 4]);
                a[mf][3] = __float_as_uint(Qs[r + 8][k8 + l4 + 4]);
            }
            #pragma unroll
            for (int nf = 0; nf < 8; nf++) {
                int n = (nf << 3) + grp;
                b[nf][0] = __float_as_uint(Ks[n][k8 + l4]);
                b[nf][1] = __float_as_uint(Ks[n][k8 + l4 + 4]);
            }
            #pragma unroll
            for (int mf = 0; mf < 2; mf++)
                #pragma unroll
                for (int nf = 0; nf < 8; nf++)
                    mma8(s[mf][nf], a[mf], b[nf]);
        }

        // online softmax (log2 domain), P stays in s registers
        #pragma unroll
        for (int mf = 0; mf < 2; mf++) {
            #pragma unroll
            for (int rr = 0; rr < 2; rr++) {
                int si = (mf << 1) + rr;
                float mx = -1e30f;
                #pragma unroll
                for (int nf = 0; nf < 8; nf++)
                    mx = fmaxf(mx, fmaxf(s[mf][nf][rr * 2], s[mf][nf][rr * 2 + 1]));
                mx = fmaxf(mx, __shfl_xor_sync(0xffffffffu, mx, 1));
                mx = fmaxf(mx, __shfl_xor_sync(0xffffffffu, mx, 2));
                float mn = fmaxf(m_i[si], mx);
                float alpha = ex2(m_i[si] - mn);
                float rs = 0.f;
                #pragma unroll
                for (int nf = 0; nf < 8; nf++) {
                    float p0 = ex2(s[mf][nf][rr * 2] - mn);
                    float p1 = ex2(s[mf][nf][rr * 2 + 1] - mn);
                    s[mf][nf][rr * 2] = p0; s[mf][nf][rr * 2 + 1] = p1;
                    rs += p0 + p1;
                }
                rs += __shfl_xor_sync(0xffffffffu, rs, 1);
                rs += __shfl_xor_sync(0xffffffffu, rs, 2);
                m_i[si] = mn;
                l_i[si] = l_i[si] * alpha + rs;
                #pragma unroll
                for (int df = 0; df < 8; df++) {
                    o[mf][df][rr * 2] *= alpha;
                    o[mf][df][rr * 2 + 1] *= alpha;
                }
            }
        }
        __syncthreads();   // all warps done reading Ks

        // issue K[kt+1] -> Ks (flies through V-wait + PV)
        if (kt < 31) {
            const float* kn = kb + (kt + 1) * 4096;
            #pragma unroll
            for (int i = 0; i < 8; i++) {
                int r = lr + (i << 3);
                cp16(ks_u + r * 272 + (lch << 4), kn + r * 64 + (lch << 2));
            }
            cp_commit();
        }
        if (kt > 0) {
            if (kt < 31) cp_wait1();  // drain V[kt]; K[kt+1] stays in flight
            else         cp_wait0();  // drain V[31]
            __syncthreads();          // Vs visible
        }

        // O += P @ V, A-fragment built from s via intra-quad shuffles
        int src0 = (lane & 28) | (l4 >> 1);
        int src1 = src0 + 2;
        int odd = l4 & 1;
        #pragma unroll
        for (int g = 0; g < 8; g++) {
            int k8 = g << 3;
            uint32_t b[8][2];
            #pragma unroll
            for (int df = 0; df < 8; df++) {
                int n = (df << 3) + grp;
                b[df][0] = __float_as_uint(Vs[k8 + l4][n]);
                b[df][1] = __float_as_uint(Vs[k8 + l4 + 4][n]);
            }
            #pragma unroll
            for (int mf = 0; mf < 2; mf++) {
                float q0 = __shfl_sync(0xffffffffu, s[mf][g][0], src0);
                float q1 = __shfl_sync(0xffffffffu, s[mf][g][1], src0);
                float q2 = __shfl_sync(0xffffffffu, s[mf][g][2], src0);
                float q3 = __shfl_sync(0xffffffffu, s[mf][g][3], src0);
                float r0 = __shfl_sync(0xffffffffu, s[mf][g][0], src1);
                float r1 = __shfl_sync(0xffffffffu, s[mf][g][1], src1);
                float r2 = __shfl_sync(0xffffffffu, s[mf][g][2], src1);
                float r3 = __shfl_sync(0xffffffffu, s[mf][g][3], src1);
                uint32_t a[4];
                a[0] = __float_as_uint(f2tf(odd ? q1 : q0));
                a[1] = __float_as_uint(f2tf(odd ? q3 : q2));
                a[2] = __float_as_uint(f2tf(odd ? r1 : r0));
                a[3] = __float_as_uint(f2tf(odd ? r3 : r2));
                #pragma unroll
                for (int df = 0; df < 8; df++)
                    mma8(o[mf][df], a, b[df]);
            }
        }

        if (kt < 31) {
            __syncthreads();   // Vs dead everywhere
            const float* vn = vb + (kt + 1) * 4096;
            #pragma unroll
            for (int i = 0; i < 8; i++) {
                int r = lr + (i << 3);
                cp16(vs_u + r * 288 + (lch << 4), vn + r * 64 + (lch << 2));
            }
            cp_commit();
            cp_wait1();        // drain K[kt+1]; V[kt+1] stays in flight
            __syncthreads();   // Ks visible for next S
        }
    }

    // epilogue: normalize + write out[b][n][h*64+d]
    int b = bh >> 4, h = bh & 15;
    #pragma unroll
    for (int mf = 0; mf < 2; mf++) {
        #pragma unroll
        for (int rr = 0; rr < 2; rr++) {
            int si = (mf << 1) + rr;
            float inv = 1.f / l_i[si];
            int n = (qt << 7) + mb + (mf << 4) + grp + (rr << 3);
            size_t base = ((size_t)(b * NN + n)) * CC + (h << 6);
            #pragma unroll
            for (int df = 0; df < 8; df++) {
                int col = (df << 3) + (l4 << 1);
                float2 vo = make_float2(o[mf][df][rr * 2] * inv,
                                        o[mf][df][rr * 2 + 1] * inv);
                *(float2*)&out[base + col] = vo;
            }
        }
    }
}

// ---------------------------------------------------------------------------
extern "C" void kernel_launch(void* const* d_in, const int* in_sizes, int n_in,
                              void* d_out, int out_size)
{
    const float* x1   = (const float*)d_in[0];
    const float* x2   = (const float*)d_in[1];
    const float* wq   = (const float*)d_in[2];
    const float* bq   = (const float*)d_in[3];
    const float* wkv  = (const float*)d_in[4];
    const float* bkv  = (const float*)d_in[5];
    const float* gmq  = (const float*)d_in[6];
    const float* btq  = (const float*)d_in[7];
    const float* gmk  = (const float*)d_in[8];
    const float* btk  = (const float*)d_in[9];
    float* out = (float*)d_out;

    cudaFuncSetAttribute(attn_kernel, cudaFuncAttributeMaxDynamicSharedMemorySize, ATTN_SMEM);
    cudaFuncSetAttribute(proj_kernel, cudaFuncAttributeMaxDynamicSharedMemorySize, PROJ_SMEM);

    proj_kernel<<<dim3(48, MM / 128), 128, PROJ_SMEM>>>(
        x1, wq, bq, x2, wkv, bkv, gmq, btq, gmk, btk);

    attn_kernel<<<dim3(NN / 128, BB * HH), 128, ATTN_SMEM>>>(out);
}

// round 7
// speedup vs baseline: 4.4092x; 1.0375x over previous
#include <cuda_runtime.h>
#include <cstdint>

#define BB 4
#define NN 2048
#define CC 1024
#define HH 16
#define DD 64
#define MM (BB*NN)          // 8192

// Scratch: q, k, v in [b*H+h][n][64] layout, stored tf32-rounded (post-LN for q,k)
// q additionally pre-scaled by 0.125*log2(e) so attention scores are in log2 domain.
__device__ float g_q[(size_t)MM * CC];
__device__ float g_k[(size_t)MM * CC];
__device__ float g_v[(size_t)MM * CC];
// tf32-pre-rounded copies of inputs (read by proj via cp.async, no cvt in hot loop)
__device__ float g_x1t[(size_t)MM * CC];
__device__ float g_x2t[(size_t)MM * CC];
__device__ float g_wqt[(size_t)CC * CC];
__device__ float g_wkvt[(size_t)CC * 2 * CC];

// ---------------------------------------------------------------------------
// helpers
// ---------------------------------------------------------------------------
__device__ __forceinline__ float f2tf(float x) {
    uint32_t u;
    asm("cvt.rna.tf32.f32 %0, %1;" : "=r"(u) : "f"(x));
    return __uint_as_float(u);
}

__device__ __forceinline__ float ex2(float x) {
    float r;
    asm("ex2.approx.ftz.f32 %0, %1;" : "=f"(r) : "f"(x));
    return r;
}

__device__ __forceinline__ uint32_t smem_u32(const void* p) {
    uint32_t a;
    asm("{ .reg .u64 t; cvta.to.shared.u64 t, %1; cvt.u32.u64 %0, t; }" : "=r"(a) : "l"(p));
    return a;
}

__device__ __forceinline__ void cp16(uint32_t dst, const void* src) {
    asm volatile("cp.async.cg.shared.global [%0], [%1], 16;" :: "r"(dst), "l"(src));
}
__device__ __forceinline__ void cp_commit() { asm volatile("cp.async.commit_group;"); }
__device__ __forceinline__ void cp_wait0()  { asm volatile("cp.async.wait_group 0;"); }
__device__ __forceinline__ void cp_wait1()  { asm volatile("cp.async.wait_group 1;"); }

__device__ __forceinline__ void mma8(float c[4], const uint32_t a[4], const uint32_t b[2]) {
    asm volatile(
        "mma.sync.aligned.m16n8k8.row.col.f32.tf32.tf32.f32 "
        "{%0,%1,%2,%3}, {%4,%5,%6,%7}, {%8,%9}, {%0,%1,%2,%3};\n"
        : "+f"(c[0]), "+f"(c[1]), "+f"(c[2]), "+f"(c[3])
        : "r"(a[0]), "r"(a[1]), "r"(a[2]), "r"(a[3]), "r"(b[0]), "r"(b[1]));
}

// ---------------------------------------------------------------------------
// Elementwise tf32 pre-rounding pass
// ---------------------------------------------------------------------------
__global__ __launch_bounds__(256) void prep_kernel(const float* __restrict__ src,
                                                   float* __restrict__ dst, int n4)
{
    int i = blockIdx.x * 256 + threadIdx.x;
    if (i < n4) {
        float4 v = ((const float4*)src)[i];
        ((float4*)dst)[i] = make_float4(f2tf(v.x), f2tf(v.y), f2tf(v.z), f2tf(v.w));
    }
}

// ---------------------------------------------------------------------------
// Projection GEMM (q + kv in one launch), tf32 MMA, cp.async double-buffered.
// Block tile 128 rows x 128 cols (2 heads); 4 warps, each 64x64 (wm x wn).
// Inputs pre-rounded to tf32 -> no cvt, no reg staging in the hot loop.
// Epilogue: bias + per-head LayerNorm (q,k), q scaled by 0.125*log2(e), tf32 store.
// ---------------------------------------------------------------------------
#define PROJ_SMEM ((2*128*36 + 2*32*136) * 4)   // 71680 bytes

__global__ __launch_bounds__(128, 3) void proj_kernel(
    const float* __restrict__ bq, const float* __restrict__ bkv,
    const float* __restrict__ gamq, const float* __restrict__ betq,
    const float* __restrict__ gamk, const float* __restrict__ betk)
{
    extern __shared__ float psm[];
    float (*As)[36]  = (float(*)[36])psm;                   // [2*128][36],  36 ≡ 4 mod 32
    float (*Bs)[136] = (float(*)[136])(psm + 2 * 128 * 36); // [2*32][136], 136 ≡ 8 mod 32

    int tid  = threadIdx.x;
    int wid  = tid >> 5, lane = tid & 31;
    int grp  = lane >> 2, l4 = lane & 3;
    int wm   = wid >> 1, wn = wid & 1;
    int m0   = blockIdx.y << 7;
    int cb   = blockIdx.x;            // 0..23

    const float *A, *W, *bias, *gam, *bet;
    float* Out; int ld, n0, do_ln, is_q, voff;
    if (cb < 8) {
        A = g_x1t; W = g_wqt; bias = bq; ld = CC; n0 = cb << 7;
        Out = g_q; do_ln = 1; is_q = 1; voff = 0; gam = gamq; bet = betq;
    } else {
        int c2 = cb - 8;
        A = g_x2t; W = g_wkvt; bias = bkv; ld = 2 * CC; n0 = c2 << 7; is_q = 0;
        if (c2 < 8) { Out = g_k; do_ln = 1; voff = 0;    gam = gamk; bet = betk; }
        else        { Out = g_v; do_ln = 0; voff = 1024; gam = gamq; bet = betq; }
    }
    int n0w = n0 + (wn << 6);          // this warp's column base (proj space)
    int head = (n0w - voff) >> 6;

    float c[4][8][4];
    #pragma unroll
    for (int mf = 0; mf < 4; mf++)
        #pragma unroll
        for (int nf = 0; nf < 8; nf++)
            #pragma unroll
            for (int i = 0; i < 4; i++) c[mf][nf][i] = 0.f;

    uint32_t as_u = smem_u32(As), bs_u = smem_u32(Bs);
    int ar = tid >> 3, ac = tid & 7;      // A: 16 rows/pass x 8 quads, 8 passes
    int br = tid >> 5, bc = tid & 31;     // B: 4 rows/pass x 32 quads, 8 passes
    const float* Ap = A + (size_t)(m0 + ar) * CC + (ac << 2);
    const float* Wp = W + (size_t)br * ld + n0 + (bc << 2);

    // prologue: chunk 0 -> buf 0
    #pragma unroll
    for (int i = 0; i < 8; i++) {
        cp16(as_u + ((ar + (i << 4)) * 36 + (ac << 2)) * 4, Ap + (size_t)(i << 4) * CC);
        cp16(bs_u + ((br + (i << 2)) * 136 + (bc << 2)) * 4, Wp + (size_t)(i << 2) * ld);
    }
    cp_commit();

    for (int ch = 0; ch < 32; ch++) {
        int buf = ch & 1;
        // issue chunk ch+1 -> buf^1 (safe: barrier at end of prev iter)
        if (ch < 31) {
            int k0 = (ch + 1) << 5;
            int ob = buf ^ 1;
            #pragma unroll
            for (int i = 0; i < 8; i++) {
                cp16(as_u + (((ob << 7) + ar + (i << 4)) * 36 + (ac << 2)) * 4,
                     Ap + (size_t)(i << 4) * CC + k0);
                cp16(bs_u + (((ob << 5) + br + (i << 2)) * 136 + (bc << 2)) * 4,
                     Wp + (size_t)(k0 + (i << 2)) * ld);
            }
            cp_commit();
            cp_wait1();
        } else {
            cp_wait0();
        }
        __syncthreads();   // chunk ch visible

        float (*Ab)[36]  = &As[buf << 7];
        float (*Bb)[136] = &Bs[buf << 5];
        #pragma unroll
        for (int ks = 0; ks < 4; ks++) {
            int k8 = ks << 3;
            uint32_t a[4][4];
            #pragma unroll
            for (int mf = 0; mf < 4; mf++) {
                int r = (wm << 6) + (mf << 4) + grp;
                a[mf][0] = __float_as_uint(Ab[r][k8 + l4]);
                a[mf][1] = __float_as_uint(Ab[r + 8][k8 + l4]);
                a[mf][2] = __float_as_uint(Ab[r][k8 + l4 + 4]);
                a[mf][3] = __float_as_uint(Ab[r + 8][k8 + l4 + 4]);
            }
            #pragma unroll
            for (int nf = 0; nf < 8; nf++) {
                int n = (wn << 6) + (nf << 3) + grp;
                uint32_t b[2];
                b[0] = __float_as_uint(Bb[k8 + l4][n]);
                b[1] = __float_as_uint(Bb[k8 + l4 + 4][n]);
                #pragma unroll
                for (int mf = 0; mf < 4; mf++)
                    mma8(c[mf][nf], a[mf], b);
            }
        }
        __syncthreads();   // all warps done with buf before it is overwritten
    }

    // Epilogue: bias + (optional) LayerNorm + (q) log2-domain scale + tf32 store
    const float SC = 0.18033688011112042f;   // 0.125 * log2(e)
    #pragma unroll
    for (int mf = 0; mf < 4; mf++) {
        float s0 = 0.f, s1 = 0.f, t0 = 0.f, t1 = 0.f;
        #pragma unroll
        for (int nf = 0; nf < 8; nf++) {
            int col = (nf << 3) + (l4 << 1);
            float b0 = bias[n0w + col], b1 = bias[n0w + col + 1];
            c[mf][nf][0] += b0; c[mf][nf][1] += b1;
            c[mf][nf][2] += b0; c[mf][nf][3] += b1;
            s0 += c[mf][nf][0] + c[mf][nf][1];
            s1 += c[mf][nf][2] + c[mf][nf][3];
            t0 += c[mf][nf][0] * c[mf][nf][0] + c[mf][nf][1] * c[mf][nf][1];
            t1 += c[mf][nf][2] * c[mf][nf][2] + c[mf][nf][3] * c[mf][nf][3];
        }
        #pragma unroll
        for (int off = 1; off <= 2; off <<= 1) {
            s0 += __shfl_xor_sync(0xffffffffu, s0, off);
            s1 += __shfl_xor_sync(0xffffffffu, s1, off);
            t0 += __shfl_xor_sync(0xffffffffu, t0, off);
            t1 += __shfl_xor_sync(0xffffffffu, t1, off);
        }
        float mean0 = 0.f, mean1 = 0.f, inv0 = 1.f, inv1 = 1.f;
        if (do_ln) {
            mean0 = s0 * 0.015625f;
            mean1 = s1 * 0.015625f;
            inv0 = rsqrtf(t0 * 0.015625f - mean0 * mean0 + 1e-5f);
            inv1 = rsqrtf(t1 * 0.015625f - mean1 * mean1 + 1e-5f);
        }

        int r0 = (wm << 6) + (mf << 4) + grp;
        int m = m0 + r0;
        int b = m >> 11, nseq = m & 2047;
        size_t base0 = (((size_t)(b * HH + head)) * NN + nseq) * DD;
        size_t base1 = base0 + (size_t)8 * DD;
        #pragma unroll
        for (int nf = 0; nf < 8; nf++) {
            int col = (nf << 3) + (l4 << 1);
            float y0 = c[mf][nf][0], y1 = c[mf][nf][1];
            float y2 = c[mf][nf][2], y3 = c[mf][nf][3];
            if (do_ln) {
                float g0 = gam[col], g1 = gam[col + 1];
                float e0 = bet[col], e1 = bet[col + 1];
                y0 = (y0 - mean0) * inv0 * g0 + e0;
                y1 = (y1 - mean0) * inv0 * g1 + e1;
                y2 = (y2 - mean1) * inv1 * g0 + e0;
                y3 = (y3 - mean1) * inv1 * g1 + e1;
            }
            if (is_q) { y0 *= SC; y1 *= SC; y2 *= SC; y3 *= SC; }
            *(float2*)&Out[base0 + col] = make_float2(f2tf(y0), f2tf(y1));
            *(float2*)&Out[base1 + col] = make_float2(f2tf(y2), f2tf(y3));
        }
    }
}

// ---------------------------------------------------------------------------
// Flash attention (tf32 MMA): 128-row Q tile/block, 4 warps (32 q-rows each),
// stream 64-row K/V tiles via cp.async. P kept in registers via intra-quad
// shuffles. 69 KB smem -> 2 CTAs/SM.
// ---------------------------------------------------------------------------
#define ATTN_SMEM ((128*68 + 64*68 + 64*72) * 4)   // 70656 bytes

__global__ __launch_bounds__(128, 2) void attn_kernel(float* __restrict__ out)
{
    extern __shared__ float sm[];
    float (*Qs)[68] = (float(*)[68])sm;                        // 128x68
    float (*Ks)[68] = (float(*)[68])(sm + 128 * 68);           // 64x68
    float (*Vs)[72] = (float(*)[72])(sm + 128 * 68 + 64 * 68); // 64x72

    int tid = threadIdx.x;
    int wid = tid >> 5, lane = tid & 31;
    int grp = lane >> 2, l4 = lane & 3;
    int bh = blockIdx.y, qt = blockIdx.x;
    int mb = wid << 5;

    const float* qb = g_q + (size_t)bh * (NN * 64) + (size_t)qt * (128 * 64);
    const float* kb = g_k + (size_t)bh * (NN * 64);
    const float* vb = g_v + (size_t)bh * (NN * 64);

    uint32_t qs_u = smem_u32(Qs), ks_u = smem_u32(Ks), vs_u = smem_u32(Vs);
    int lr = tid >> 4, lch = tid & 15;

    #pragma unroll
    for (int i = 0; i < 8; i++) {
        int r = lr + (i << 3);
        cp16(qs_u + r * 272 + (lch << 4), qb + r * 64 + (lch << 2));
        cp16(qs_u + (r + 64) * 272 + (lch << 4), qb + (r + 64) * 64 + (lch << 2));
        cp16(ks_u + r * 272 + (lch << 4), kb + r * 64 + (lch << 2));
        cp16(vs_u + r * 288 + (lch << 4), vb + r * 64 + (lch << 2));
    }
    cp_commit();
    cp_wait0();
    __syncthreads();

    float o[2][8][4];
    #pragma unroll
    for (int mf = 0; mf < 2; mf++)
        #pragma unroll
        for (int df = 0; df < 8; df++)
            #pragma unroll
            for (int i = 0; i < 4; i++) o[mf][df][i] = 0.f;
    float m_i[4] = {-1e30f, -1e30f, -1e30f, -1e30f};
    float l_i[4] = {0.f, 0.f, 0.f, 0.f};

    for (int kt = 0; kt < 32; kt++) {
        float s[2][8][4];
        #pragma unroll
        for (int mf = 0; mf < 2; mf++)
            #pragma unroll
            for (int nf = 0; nf < 8; nf++)
                #pragma unroll
                for (int i = 0; i < 4; i++) s[mf][nf][i] = 0.f;

        #pragma unroll
        for (int ks8 = 0; ks8 < 8; ks8++) {
            int k8 = ks8 << 3;
            uint32_t a[2][4], b[8][2];
            #pragma unroll
            for (int mf = 0; mf < 2; mf++) {
                int r = mb + (mf << 4) + grp;
                a[mf][0] = __float_as_uint(Qs[r][k8 + l4]);
                a[mf][1] = __float_as_uint(Qs[r + 8][k8 + l4]);
                a[mf][2] = __float_as_uint(Qs[r][k8 + l4 + 4]);
                a[mf][3] = __float_as_uint(Qs[r + 8][k8 + l4 + 4]);
            }
            #pragma unroll
            for (int nf = 0; nf < 8; nf++) {
                int n = (nf << 3) + grp;
                b[nf][0] = __float_as_uint(Ks[n][k8 + l4]);
                b[nf][1] = __float_as_uint(Ks[n][k8 + l4 + 4]);
            }
            #pragma unroll
            for (int mf = 0; mf < 2; mf++)
                #pragma unroll
                for (int nf = 0; nf < 8; nf++)
                    mma8(s[mf][nf], a[mf], b[nf]);
        }

        // online softmax (log2 domain)
        #pragma unroll
        for (int mf = 0; mf < 2; mf++) {
            #pragma unroll
            for (int rr = 0; rr < 2; rr++) {
                int si = (mf << 1) + rr;
                float mx = -1e30f;
                #pragma unroll
                for (int nf = 0; nf < 8; nf++)
                    mx = fmaxf(mx, fmaxf(s[mf][nf][rr * 2], s[mf][nf][rr * 2 + 1]));
                mx = fmaxf(mx, __shfl_xor_sync(0xffffffffu, mx, 1));
                mx = fmaxf(mx, __shfl_xor_sync(0xffffffffu, mx, 2));
                float mn = fmaxf(m_i[si], mx);
                float alpha = ex2(m_i[si] - mn);
                float rs = 0.f;
                #pragma unroll
                for (int nf = 0; nf < 8; nf++) {
                    float p0 = ex2(s[mf][nf][rr * 2] - mn);
                    float p1 = ex2(s[mf][nf][rr * 2 + 1] - mn);
                    s[mf][nf][rr * 2] = p0; s[mf][nf][rr * 2 + 1] = p1;
                    rs += p0 + p1;
                }
                rs += __shfl_xor_sync(0xffffffffu, rs, 1);
                rs += __shfl_xor_sync(0xffffffffu, rs, 2);
                m_i[si] = mn;
                l_i[si] = l_i[si] * alpha + rs;
                #pragma unroll
                for (int df = 0; df < 8; df++) {
                    o[mf][df][rr * 2] *= alpha;
                    o[mf][df][rr * 2 + 1] *= alpha;
                }
            }
        }
        __syncthreads();   // all warps done reading Ks

        if (kt < 31) {
            const float* kn = kb + (kt + 1) * 4096;
            #pragma unroll
            for (int i = 0; i < 8; i++) {
                int r = lr + (i << 3);
                cp16(ks_u + r * 272 + (lch << 4), kn + r * 64 + (lch << 2));
            }
            cp_commit();
        }
        if (kt > 0) {
            if (kt < 31) cp_wait1();
            else         cp_wait0();
            __syncthreads();
        }

        // O += P @ V, A-fragment built via intra-quad shuffles
        int src0 = (lane & 28) | (l4 >> 1);
        int src1 = src0 + 2;
        int odd = l4 & 1;
        #pragma unroll
        for (int g = 0; g < 8; g++) {
            int k8 = g << 3;
            uint32_t b[8][2];
            #pragma unroll
            for (int df = 0; df < 8; df++) {
                int n = (df << 3) + grp;
                b[df][0] = __float_as_uint(Vs[k8 + l4][n]);
                b[df][1] = __float_as_uint(Vs[k8 + l4 + 4][n]);
            }
            #pragma unroll
            for (int mf = 0; mf < 2; mf++) {
                float q0 = __shfl_sync(0xffffffffu, s[mf][g][0], src0);
                float q1 = __shfl_sync(0xffffffffu, s[mf][g][1], src0);
                float q2 = __shfl_sync(0xffffffffu, s[mf][g][2], src0);
                float q3 = __shfl_sync(0xffffffffu, s[mf][g][3], src0);
                float r0 = __shfl_sync(0xffffffffu, s[mf][g][0], src1);
                float r1 = __shfl_sync(0xffffffffu, s[mf][g][1], src1);
                float r2 = __shfl_sync(0xffffffffu, s[mf][g][2], src1);
                float r3 = __shfl_sync(0xffffffffu, s[mf][g][3], src1);
                uint32_t a[4];
                a[0] = __float_as_uint(f2tf(odd ? q1 : q0));
                a[1] = __float_as_uint(f2tf(odd ? q3 : q2));
                a[2] = __float_as_uint(f2tf(odd ? r1 : r0));
                a[3] = __float_as_uint(f2tf(odd ? r3 : r2));
                #pragma unroll
                for (int df = 0; df < 8; df++)
                    mma8(o[mf][df], a, b[df]);
            }
        }

        if (kt < 31) {
            __syncthreads();
            const float* vn = vb + (kt + 1) * 4096;
            #pragma unroll
            for (int i = 0; i < 8; i++) {
                int r = lr + (i << 3);
                cp16(vs_u + r * 288 + (lch << 4), vn + r * 64 + (lch << 2));
            }
            cp_commit();
            cp_wait1();
            __syncthreads();
        }
    }

    int b = bh >> 4, h = bh & 15;
    #pragma unroll
    for (int mf = 0; mf < 2; mf++) {
        #pragma unroll
        for (int rr = 0; rr < 2; rr++) {
            int si = (mf << 1) + rr;
            float inv = 1.f / l_i[si];
            int n = (qt << 7) + mb + (mf << 4) + grp + (rr << 3);
            size_t base = ((size_t)(b * NN + n)) * CC + (h << 6);
            #pragma unroll
            for (int df = 0; df < 8; df++) {
                int col = (df << 3) + (l4 << 1);
                float2 vo = make_float2(o[mf][df][rr * 2] * inv,
                                        o[mf][df][rr * 2 + 1] * inv);
                *(float2*)&out[base + col] = vo;
            }
        }
    }
}

// ---------------------------------------------------------------------------
extern "C" void kernel_launch(void* const* d_in, const int* in_sizes, int n_in,
                              void* d_out, int out_size)
{
    const float* x1   = (const float*)d_in[0];
    const float* x2   = (const float*)d_in[1];
    const float* wq   = (const float*)d_in[2];
    const float* bq   = (const float*)d_in[3];
    const float* wkv  = (const float*)d_in[4];
    const float* bkv  = (const float*)d_in[5];
    const float* gmq  = (const float*)d_in[6];
    const float* btq  = (const float*)d_in[7];
    const float* gmk  = (const float*)d_in[8];
    const float* btk  = (const float*)d_in[9];
    float* out = (float*)d_out;

    cudaFuncSetAttribute(attn_kernel, cudaFuncAttributeMaxDynamicSharedMemorySize, ATTN_SMEM);
    cudaFuncSetAttribute(proj_kernel, cudaFuncAttributeMaxDynamicSharedMemorySize, PROJ_SMEM);

    float *dx1t, *dx2t, *dwqt, *dwkvt;
    cudaGetSymbolAddress((void**)&dx1t, g_x1t);
    cudaGetSymbolAddress((void**)&dx2t, g_x2t);
    cudaGetSymbolAddress((void**)&dwqt, g_wqt);
    cudaGetSymbolAddress((void**)&dwkvt, g_wkvt);

    prep_kernel<<<(MM * CC / 4) / 256, 256>>>(x1, dx1t, MM * CC / 4);
    prep_kernel<<<(MM * CC / 4) / 256, 256>>>(x2, dx2t, MM * CC / 4);
    prep_kernel<<<(CC * CC / 4) / 256, 256>>>(wq, dwqt, CC * CC / 4);
    prep_kernel<<<(CC * 2 * CC / 4) / 256, 256>>>(wkv, dwkvt, CC * 2 * CC / 4);

    proj_kernel<<<dim3(24, MM / 128), 128, PROJ_SMEM>>>(bq, bkv, gmq, btq, gmk, btk);

    attn_kernel<<<dim3(NN / 128, BB * HH), 128, ATTN_SMEM>>>(out);
}

// round 8
// speedup vs baseline: 4.5312x; 1.0277x over previous
#include <cuda_runtime.h>
#include <cstdint>

#define BB 4
#define NN 2048
#define CC 1024
#define HH 16
#define DD 64
#define MM (BB*NN)          // 8192

// Scratch: q, k, v in [b*H+h][n][64] layout, stored tf32-rounded (post-LN for q,k)
// q additionally pre-scaled by 0.125*log2(e) so attention scores are in log2 domain.
__device__ float g_q[(size_t)MM * CC];
__device__ float g_k[(size_t)MM * CC];
__device__ float g_v[(size_t)MM * CC];
// tf32-pre-rounded copies of inputs (read by proj via cp.async, no cvt in hot loop)
__device__ float g_x1t[(size_t)MM * CC];
__device__ float g_x2t[(size_t)MM * CC];
__device__ float g_wqt[(size_t)CC * CC];
__device__ float g_wkvt[(size_t)CC * 2 * CC];

// ---------------------------------------------------------------------------
// helpers
// ---------------------------------------------------------------------------
__device__ __forceinline__ float f2tf(float x) {
    uint32_t u;
    asm("cvt.rna.tf32.f32 %0, %1;" : "=r"(u) : "f"(x));
    return __uint_as_float(u);
}

__device__ __forceinline__ float ex2(float x) {
    float r;
    asm("ex2.approx.ftz.f32 %0, %1;" : "=f"(r) : "f"(x));
    return r;
}

__device__ __forceinline__ uint32_t smem_u32(const void* p) {
    uint32_t a;
    asm("{ .reg .u64 t; cvta.to.shared.u64 t, %1; cvt.u32.u64 %0, t; }" : "=r"(a) : "l"(p));
    return a;
}

__device__ __forceinline__ void cp16(uint32_t dst, const void* src) {
    asm volatile("cp.async.cg.shared.global [%0], [%1], 16;" :: "r"(dst), "l"(src));
}
__device__ __forceinline__ void cp_commit() { asm volatile("cp.async.commit_group;"); }
__device__ __forceinline__ void cp_wait0()  { asm volatile("cp.async.wait_group 0;"); }
__device__ __forceinline__ void cp_wait1()  { asm volatile("cp.async.wait_group 1;"); }

__device__ __forceinline__ void mma8(float c[4], const uint32_t a[4], const uint32_t b[2]) {
    asm volatile(
        "mma.sync.aligned.m16n8k8.row.col.f32.tf32.tf32.f32 "
        "{%0,%1,%2,%3}, {%4,%5,%6,%7}, {%8,%9}, {%0,%1,%2,%3};\n"
        : "+f"(c[0]), "+f"(c[1]), "+f"(c[2]), "+f"(c[3])
        : "r"(a[0]), "r"(a[1]), "r"(a[2]), "r"(a[3]), "r"(b[0]), "r"(b[1]));
}

// ---------------------------------------------------------------------------
// Elementwise tf32 pre-rounding pass
// ---------------------------------------------------------------------------
__global__ __launch_bounds__(256) void prep_kernel(const float* __restrict__ src,
                                                   float* __restrict__ dst, int n4)
{
    int i = blockIdx.x * 256 + threadIdx.x;
    if (i < n4) {
        float4 v = ((const float4*)src)[i];
        ((float4*)dst)[i] = make_float4(f2tf(v.x), f2tf(v.y), f2tf(v.z), f2tf(v.w));
    }
}

// ---------------------------------------------------------------------------
// Projection GEMM (q + kv in one launch), tf32 MMA, cp.async double-buffered.
// Block tile 128 rows x 128 cols (2 heads); 4 warps, each 64x64 (wm x wn).
// Epilogue: bias + per-head LayerNorm (q,k), q scaled by 0.125*log2(e), tf32 store.
// ---------------------------------------------------------------------------
#define PROJ_SMEM ((2*128*36 + 2*32*136) * 4)   // 71680 bytes

__global__ __launch_bounds__(128, 3) void proj_kernel(
    const float* __restrict__ bq, const float* __restrict__ bkv,
    const float* __restrict__ gamq, const float* __restrict__ betq,
    const float* __restrict__ gamk, const float* __restrict__ betk)
{
    extern __shared__ float psm[];
    float (*As)[36]  = (float(*)[36])psm;                   // [2*128][36],  36 ≡ 4 mod 32
    float (*Bs)[136] = (float(*)[136])(psm + 2 * 128 * 36); // [2*32][136], 136 ≡ 8 mod 32

    int tid  = threadIdx.x;
    int wid  = tid >> 5, lane = tid & 31;
    int grp  = lane >> 2, l4 = lane & 3;
    int wm   = wid >> 1, wn = wid & 1;
    int m0   = blockIdx.y << 7;
    int cb   = blockIdx.x;            // 0..23

    const float *A, *W, *bias, *gam, *bet;
    float* Out; int ld, n0, do_ln, is_q, voff;
    if (cb < 8) {
        A = g_x1t; W = g_wqt; bias = bq; ld = CC; n0 = cb << 7;
        Out = g_q; do_ln = 1; is_q = 1; voff = 0; gam = gamq; bet = betq;
    } else {
        int c2 = cb - 8;
        A = g_x2t; W = g_wkvt; bias = bkv; ld = 2 * CC; n0 = c2 << 7; is_q = 0;
        if (c2 < 8) { Out = g_k; do_ln = 1; voff = 0;    gam = gamk; bet = betk; }
        else        { Out = g_v; do_ln = 0; voff = 1024; gam = gamq; bet = betq; }
    }
    int n0w = n0 + (wn << 6);
    int head = (n0w - voff) >> 6;

    float c[4][8][4];
    #pragma unroll
    for (int mf = 0; mf < 4; mf++)
        #pragma unroll
        for (int nf = 0; nf < 8; nf++)
            #pragma unroll
            for (int i = 0; i < 4; i++) c[mf][nf][i] = 0.f;

    uint32_t as_u = smem_u32(As), bs_u = smem_u32(Bs);
    int ar = tid >> 3, ac = tid & 7;
    int br = tid >> 5, bc = tid & 31;
    const float* Ap = A + (size_t)(m0 + ar) * CC + (ac << 2);
    const float* Wp = W + (size_t)br * ld + n0 + (bc << 2);

    #pragma unroll
    for (int i = 0; i < 8; i++) {
        cp16(as_u + ((ar + (i << 4)) * 36 + (ac << 2)) * 4, Ap + (size_t)(i << 4) * CC);
        cp16(bs_u + ((br + (i << 2)) * 136 + (bc << 2)) * 4, Wp + (size_t)(i << 2) * ld);
    }
    cp_commit();

    for (int ch = 0; ch < 32; ch++) {
        int buf = ch & 1;
        if (ch < 31) {
            int k0 = (ch + 1) << 5;
            int ob = buf ^ 1;
            #pragma unroll
            for (int i = 0; i < 8; i++) {
                cp16(as_u + (((ob << 7) + ar + (i << 4)) * 36 + (ac << 2)) * 4,
                     Ap + (size_t)(i << 4) * CC + k0);
                cp16(bs_u + (((ob << 5) + br + (i << 2)) * 136 + (bc << 2)) * 4,
                     Wp + (size_t)(k0 + (i << 2)) * ld);
            }
            cp_commit();
            cp_wait1();
        } else {
            cp_wait0();
        }
        __syncthreads();

        float (*Ab)[36]  = &As[buf << 7];
        float (*Bb)[136] = &Bs[buf << 5];
        #pragma unroll
        for (int ks = 0; ks < 4; ks++) {
            int k8 = ks << 3;
            uint32_t a[4][4];
            #pragma unroll
            for (int mf = 0; mf < 4; mf++) {
                int r = (wm << 6) + (mf << 4) + grp;
                a[mf][0] = __float_as_uint(Ab[r][k8 + l4]);
                a[mf][1] = __float_as_uint(Ab[r + 8][k8 + l4]);
                a[mf][2] = __float_as_uint(Ab[r][k8 + l4 + 4]);
                a[mf][3] = __float_as_uint(Ab[r + 8][k8 + l4 + 4]);
            }
            #pragma unroll
            for (int nf = 0; nf < 8; nf++) {
                int n = (wn << 6) + (nf << 3) + grp;
                uint32_t b[2];
                b[0] = __float_as_uint(Bb[k8 + l4][n]);
                b[1] = __float_as_uint(Bb[k8 + l4 + 4][n]);
                #pragma unroll
                for (int mf = 0; mf < 4; mf++)
                    mma8(c[mf][nf], a[mf], b);
            }
        }
        __syncthreads();
    }

    const float SC = 0.18033688011112042f;   // 0.125 * log2(e)
    #pragma unroll
    for (int mf = 0; mf < 4; mf++) {
        float s0 = 0.f, s1 = 0.f, t0 = 0.f, t1 = 0.f;
        #pragma unroll
        for (int nf = 0; nf < 8; nf++) {
            int col = (nf << 3) + (l4 << 1);
            float b0 = bias[n0w + col], b1 = bias[n0w + col + 1];
            c[mf][nf][0] += b0; c[mf][nf][1] += b1;
            c[mf][nf][2] += b0; c[mf][nf][3] += b1;
            s0 += c[mf][nf][0] + c[mf][nf][1];
            s1 += c[mf][nf][2] + c[mf][nf][3];
            t0 += c[mf][nf][0] * c[mf][nf][0] + c[mf][nf][1] * c[mf][nf][1];
            t1 += c[mf][nf][2] * c[mf][nf][2] + c[mf][nf][3] * c[mf][nf][3];
        }
        #pragma unroll
        for (int off = 1; off <= 2; off <<= 1) {
            s0 += __shfl_xor_sync(0xffffffffu, s0, off);
            s1 += __shfl_xor_sync(0xffffffffu, s1, off);
            t0 += __shfl_xor_sync(0xffffffffu, t0, off);
            t1 += __shfl_xor_sync(0xffffffffu, t1, off);
        }
        float mean0 = 0.f, mean1 = 0.f, inv0 = 1.f, inv1 = 1.f;
        if (do_ln) {
            mean0 = s0 * 0.015625f;
            mean1 = s1 * 0.015625f;
            inv0 = rsqrtf(t0 * 0.015625f - mean0 * mean0 + 1e-5f);
            inv1 = rsqrtf(t1 * 0.015625f - mean1 * mean1 + 1e-5f);
        }

        int r0 = (wm << 6) + (mf << 4) + grp;
        int m = m0 + r0;
        int b = m >> 11, nseq = m & 2047;
        size_t base0 = (((size_t)(b * HH + head)) * NN + nseq) * DD;
        size_t base1 = base0 + (size_t)8 * DD;
        #pragma unroll
        for (int nf = 0; nf < 8; nf++) {
            int col = (nf << 3) + (l4 << 1);
            float y0 = c[mf][nf][0], y1 = c[mf][nf][1];
            float y2 = c[mf][nf][2], y3 = c[mf][nf][3];
            if (do_ln) {
                float g0 = gam[col], g1 = gam[col + 1];
                float e0 = bet[col], e1 = bet[col + 1];
                y0 = (y0 - mean0) * inv0 * g0 + e0;
                y1 = (y1 - mean0) * inv0 * g1 + e1;
                y2 = (y2 - mean1) * inv1 * g0 + e0;
                y3 = (y3 - mean1) * inv1 * g1 + e1;
            }
            if (is_q) { y0 *= SC; y1 *= SC; y2 *= SC; y3 *= SC; }
            *(float2*)&Out[base0 + col] = make_float2(f2tf(y0), f2tf(y1));
            *(float2*)&Out[base1 + col] = make_float2(f2tf(y2), f2tf(y3));
        }
    }
}

// ---------------------------------------------------------------------------
// Flash attention (tf32 MMA), NO online softmax: scores are bounded after LN
// (|log2-score| <~ 8), so we accumulate unnormalized exp2 directly in fp32.
// Per-thread partial row sums; single shuffle reduction in the epilogue.
// 128-row Q tile/block, 4 warps, cp.async K/V streaming. 69 KB smem, 2 CTAs/SM.
// ---------------------------------------------------------------------------
#define ATTN_SMEM ((128*68 + 64*68 + 64*72) * 4)   // 70656 bytes

__global__ __launch_bounds__(128, 2) void attn_kernel(float* __restrict__ out)
{
    extern __shared__ float sm[];
    float (*Qs)[68] = (float(*)[68])sm;                        // 128x68
    float (*Ks)[68] = (float(*)[68])(sm + 128 * 68);           // 64x68
    float (*Vs)[72] = (float(*)[72])(sm + 128 * 68 + 64 * 68); // 64x72

    int tid = threadIdx.x;
    int wid = tid >> 5, lane = tid & 31;
    int grp = lane >> 2, l4 = lane & 3;
    int bh = blockIdx.y, qt = blockIdx.x;
    int mb = wid << 5;

    const float* qb = g_q + (size_t)bh * (NN * 64) + (size_t)qt * (128 * 64);
    const float* kb = g_k + (size_t)bh * (NN * 64);
    const float* vb = g_v + (size_t)bh * (NN * 64);

    uint32_t qs_u = smem_u32(Qs), ks_u = smem_u32(Ks), vs_u = smem_u32(Vs);
    int lr = tid >> 4, lch = tid & 15;

    #pragma unroll
    for (int i = 0; i < 8; i++) {
        int r = lr + (i << 3);
        cp16(qs_u + r * 272 + (lch << 4), qb + r * 64 + (lch << 2));
        cp16(qs_u + (r + 64) * 272 + (lch << 4), qb + (r + 64) * 64 + (lch << 2));
        cp16(ks_u + r * 272 + (lch << 4), kb + r * 64 + (lch << 2));
        cp16(vs_u + r * 288 + (lch << 4), vb + r * 64 + (lch << 2));
    }
    cp_commit();
    cp_wait0();
    __syncthreads();

    float o[2][8][4];
    #pragma unroll
    for (int mf = 0; mf < 2; mf++)
        #pragma unroll
        for (int df = 0; df < 8; df++)
            #pragma unroll
            for (int i = 0; i < 4; i++) o[mf][df][i] = 0.f;
    float l_i[4] = {0.f, 0.f, 0.f, 0.f};   // per-thread partial row sums

    for (int kt = 0; kt < 32; kt++) {
        // S = Q @ K^T (log2 domain: q pre-scaled by 0.125*log2e)
        float s[2][8][4];
        #pragma unroll
        for (int mf = 0; mf < 2; mf++)
            #pragma unroll
            for (int nf = 0; nf < 8; nf++)
                #pragma unroll
                for (int i = 0; i < 4; i++) s[mf][nf][i] = 0.f;

        #pragma unroll
        for (int ks8 = 0; ks8 < 8; ks8++) {
            int k8 = ks8 << 3;
            uint32_t a[2][4], b[8][2];
            #pragma unroll
            for (int mf = 0; mf < 2; mf++) {
                int r = mb + (mf << 4) + grp;
                a[mf][0] = __float_as_uint(Qs[r][k8 + l4]);
                a[mf][1] = __float_as_uint(Qs[r + 8][k8 + l4]);
                a[mf][2] = __float_as_uint(Qs[r][k8 + l4 + 4]);
                a[mf][3] = __float_as_uint(Qs[r + 8][k8 + l4 + 4]);
            }
            #pragma unroll
            for (int nf = 0; nf < 8; nf++) {
                int n = (nf << 3) + grp;
                b[nf][0] = __float_as_uint(Ks[n][k8 + l4]);
                b[nf][1] = __float_as_uint(Ks[n][k8 + l4 + 4]);
            }
            #pragma unroll
            for (int mf = 0; mf < 2; mf++)
                #pragma unroll
                for (int nf = 0; nf < 8; nf++)
                    mma8(s[mf][nf], a[mf], b[nf]);
        }

        // p = exp2(s), accumulate per-thread row sums (no max, no rescale)
        #pragma unroll
        for (int mf = 0; mf < 2; mf++)
            #pragma unroll
            for (int nf = 0; nf < 8; nf++) {
                float p0 = ex2(s[mf][nf][0]);
                float p1 = ex2(s[mf][nf][1]);
                float p2 = ex2(s[mf][nf][2]);
                float p3 = ex2(s[mf][nf][3]);
                s[mf][nf][0] = p0; s[mf][nf][1] = p1;
                s[mf][nf][2] = p2; s[mf][nf][3] = p3;
                l_i[mf << 1]       += p0 + p1;
                l_i[(mf << 1) + 1] += p2 + p3;
            }
        __syncthreads();   // all warps done reading Ks

        if (kt < 31) {
            const float* kn = kb + (kt + 1) * 4096;
            #pragma unroll
            for (int i = 0; i < 8; i++) {
                int r = lr + (i << 3);
                cp16(ks_u + r * 272 + (lch << 4), kn + r * 64 + (lch << 2));
            }
            cp_commit();
        }
        if (kt > 0) {
            if (kt < 31) cp_wait1();
            else         cp_wait0();
            __syncthreads();
        }

        // O += P @ V, A-fragment built via intra-quad shuffles
        int src0 = (lane & 28) | (l4 >> 1);
        int src1 = src0 + 2;
        int odd = l4 & 1;
        #pragma unroll
        for (int g = 0; g < 8; g++) {
            int k8 = g << 3;
            uint32_t b[8][2];
            #pragma unroll
            for (int df = 0; df < 8; df++) {
                int n = (df << 3) + grp;
                b[df][0] = __float_as_uint(Vs[k8 + l4][n]);
                b[df][1] = __float_as_uint(Vs[k8 + l4 + 4][n]);
            }
            #pragma unroll
            for (int mf = 0; mf < 2; mf++) {
                float q0 = __shfl_sync(0xffffffffu, s[mf][g][0], src0);
                float q1 = __shfl_sync(0xffffffffu, s[mf][g][1], src0);
                float q2 = __shfl_sync(0xffffffffu, s[mf][g][2], src0);
                float q3 = __shfl_sync(0xffffffffu, s[mf][g][3], src0);
                float r0 = __shfl_sync(0xffffffffu, s[mf][g][0], src1);
                float r1 = __shfl_sync(0xffffffffu, s[mf][g][1], src1);
                float r2 = __shfl_sync(0xffffffffu, s[mf][g][2], src1);
                float r3 = __shfl_sync(0xffffffffu, s[mf][g][3], src1);
                uint32_t a[4];
                a[0] = __float_as_uint(f2tf(odd ? q1 : q0));
                a[1] = __float_as_uint(f2tf(odd ? q3 : q2));
                a[2] = __float_as_uint(f2tf(odd ? r1 : r0));
                a[3] = __float_as_uint(f2tf(odd ? r3 : r2));
                #pragma unroll
                for (int df = 0; df < 8; df++)
                    mma8(o[mf][df], a, b[df]);
            }
        }

        if (kt < 31) {
            __syncthreads();
            const float* vn = vb + (kt + 1) * 4096;
            #pragma unroll
            for (int i = 0; i < 8; i++) {
                int r = lr + (i << 3);
                cp16(vs_u + r * 288 + (lch << 4), vn + r * 64 + (lch << 2));
            }
            cp_commit();
            cp_wait1();
            __syncthreads();
        }
    }

    // epilogue: reduce row sums across quad, normalize, write out[b][n][h*64+d]
    #pragma unroll
    for (int si = 0; si < 4; si++) {
        l_i[si] += __shfl_xor_sync(0xffffffffu, l_i[si], 1);
        l_i[si] += __shfl_xor_sync(0xffffffffu, l_i[si], 2);
    }
    int b = bh >> 4, h = bh & 15;
    #pragma unroll
    for (int mf = 0; mf < 2; mf++) {
        #pragma unroll
        for (int rr = 0; rr < 2; rr++) {
            int si = (mf << 1) + rr;
            float inv = 1.f / l_i[si];
            int n = (qt << 7) + mb + (mf << 4) + grp + (rr << 3);
            size_t base = ((size_t)(b * NN + n)) * CC + (h << 6);
            #pragma unroll
            for (int df = 0; df < 8; df++) {
                int col = (df << 3) + (l4 << 1);
                float2 vo = make_float2(o[mf][df][rr * 2] * inv,
                                        o[mf][df][rr * 2 + 1] * inv);
                *(float2*)&out[base + col] = vo;
            }
        }
    }
}

// ---------------------------------------------------------------------------
extern "C" void kernel_launch(void* const* d_in, const int* in_sizes, int n_in,
                              void* d_out, int out_size)
{
    const float* x1   = (const float*)d_in[0];
    const float* x2   = (const float*)d_in[1];
    const float* wq   = (const float*)d_in[2];
    const float* bq   = (const float*)d_in[3];
    const float* wkv  = (const float*)d_in[4];
    const float* bkv  = (const float*)d_in[5];
    const float* gmq  = (const float*)d_in[6];
    const float* btq  = (const float*)d_in[7];
    const float* gmk  = (const float*)d_in[8];
    const float* btk  = (const float*)d_in[9];
    float* out = (float*)d_out;

    cudaFuncSetAttribute(attn_kernel, cudaFuncAttributeMaxDynamicSharedMemorySize, ATTN_SMEM);
    cudaFuncSetAttribute(proj_kernel, cudaFuncAttributeMaxDynamicSharedMemorySize, PROJ_SMEM);

    float *dx1t, *dx2t, *dwqt, *dwkvt;
    cudaGetSymbolAddress((void**)&dx1t, g_x1t);
    cudaGetSymbolAddress((void**)&dx2t, g_x2t);
    cudaGetSymbolAddress((void**)&dwqt, g_wqt);
    cudaGetSymbolAddress((void**)&dwkvt, g_wkvt);

    prep_kernel<<<(MM * CC / 4) / 256, 256>>>(x1, dx1t, MM * CC / 4);
    prep_kernel<<<(MM * CC / 4) / 256, 256>>>(x2, dx2t, MM * CC / 4);
    prep_kernel<<<(CC * CC / 4) / 256, 256>>>(wq, dwqt, CC * CC / 4);
    prep_kernel<<<(CC * 2 * CC / 4) / 256, 256>>>(wkv, dwkvt, CC * 2 * CC / 4);

    proj_kernel<<<dim3(24, MM / 128), 128, PROJ_SMEM>>>(bq, bkv, gmq, btq, gmk, btk);

    attn_kernel<<<dim3(NN / 128, BB * HH), 128, ATTN_SMEM>>>(out);
}

// round 9
// speedup vs baseline: 4.7973x; 1.0587x over previous
#include <cuda_runtime.h>
#include <cstdint>

#define BB 4
#define NN 2048
#define CC 1024
#define HH 16
#define DD 64
#define MM (BB*NN)          // 8192

// Scratch: q, k, v in [b*H+h][n][64] layout, stored tf32-rounded (post-LN for q,k)
// q additionally pre-scaled by 0.125*log2(e) so attention scores are in log2 domain.
__device__ float g_q[(size_t)MM * CC];
__device__ float g_k[(size_t)MM * CC];
__device__ float g_v[(size_t)MM * CC];
// tf32-pre-rounded copies of inputs (read by proj via cp.async, no cvt in hot loop)
__device__ float g_x1t[(size_t)MM * CC];
__device__ float g_x2t[(size_t)MM * CC];
__device__ float g_wqt[(size_t)CC * CC];
__device__ float g_wkvt[(size_t)CC * 2 * CC];

// ---------------------------------------------------------------------------
// helpers
// ---------------------------------------------------------------------------
__device__ __forceinline__ float f2tf(float x) {
    uint32_t u;
    asm("cvt.rna.tf32.f32 %0, %1;" : "=r"(u) : "f"(x));
    return __uint_as_float(u);
}

__device__ __forceinline__ float ex2(float x) {
    float r;
    asm("ex2.approx.ftz.f32 %0, %1;" : "=f"(r) : "f"(x));
    return r;
}

__device__ __forceinline__ uint32_t smem_u32(const void* p) {
    uint32_t a;
    asm("{ .reg .u64 t; cvta.to.shared.u64 t, %1; cvt.u32.u64 %0, t; }" : "=r"(a) : "l"(p));
    return a;
}

__device__ __forceinline__ void cp16(uint32_t dst, const void* src) {
    asm volatile("cp.async.cg.shared.global [%0], [%1], 16;" :: "r"(dst), "l"(src));
}
__device__ __forceinline__ void cp_commit() { asm volatile("cp.async.commit_group;"); }
__device__ __forceinline__ void cp_wait0()  { asm volatile("cp.async.wait_group 0;"); }
__device__ __forceinline__ void cp_wait1()  { asm volatile("cp.async.wait_group 1;"); }

__device__ __forceinline__ void mma8(float c[4], const uint32_t a[4], const uint32_t b[2]) {
    asm volatile(
        "mma.sync.aligned.m16n8k8.row.col.f32.tf32.tf32.f32 "
        "{%0,%1,%2,%3}, {%4,%5,%6,%7}, {%8,%9}, {%0,%1,%2,%3};\n"
        : "+f"(c[0]), "+f"(c[1]), "+f"(c[2]), "+f"(c[3])
        : "r"(a[0]), "r"(a[1]), "r"(a[2]), "r"(a[3]), "r"(b[0]), "r"(b[1]));
}

// ---------------------------------------------------------------------------
// Elementwise tf32 pre-rounding pass
// ---------------------------------------------------------------------------
__global__ __launch_bounds__(256) void prep_kernel(const float* __restrict__ src,
                                                   float* __restrict__ dst, int n4)
{
    int i = blockIdx.x * 256 + threadIdx.x;
    if (i < n4) {
        float4 v = ((const float4*)src)[i];
        ((float4*)dst)[i] = make_float4(f2tf(v.x), f2tf(v.y), f2tf(v.z), f2tf(v.w));
    }
}

// ---------------------------------------------------------------------------
// Projection GEMM (q + kv in one launch), tf32 MMA, cp.async double-buffered.
// Block tile 128 rows x 128 cols (2 heads); 4 warps, each 64x64 (wm x wn).
// Epilogue: bias + per-head LayerNorm (q,k), q scaled by 0.125*log2(e), tf32 store.
// ---------------------------------------------------------------------------
#define PROJ_SMEM ((2*128*36 + 2*32*136) * 4)   // 71680 bytes

__global__ __launch_bounds__(128, 3) void proj_kernel(
    const float* __restrict__ bq, const float* __restrict__ bkv,
    const float* __restrict__ gamq, const float* __restrict__ betq,
    const float* __restrict__ gamk, const float* __restrict__ betk)
{
    extern __shared__ float psm[];
    float (*As)[36]  = (float(*)[36])psm;                   // [2*128][36],  36 ≡ 4 mod 32
    float (*Bs)[136] = (float(*)[136])(psm + 2 * 128 * 36); // [2*32][136], 136 ≡ 8 mod 32

    int tid  = threadIdx.x;
    int wid  = tid >> 5, lane = tid & 31;
    int grp  = lane >> 2, l4 = lane & 3;
    int wm   = wid >> 1, wn = wid & 1;
    int m0   = blockIdx.y << 7;
    int cb   = blockIdx.x;            // 0..23

    const float *A, *W, *bias, *gam, *bet;
    float* Out; int ld, n0, do_ln, is_q, voff;
    if (cb < 8) {
        A = g_x1t; W = g_wqt; bias = bq; ld = CC; n0 = cb << 7;
        Out = g_q; do_ln = 1; is_q = 1; voff = 0; gam = gamq; bet = betq;
    } else {
        int c2 = cb - 8;
        A = g_x2t; W = g_wkvt; bias = bkv; ld = 2 * CC; n0 = c2 << 7; is_q = 0;
        if (c2 < 8) { Out = g_k; do_ln = 1; voff = 0;    gam = gamk; bet = betk; }
        else        { Out = g_v; do_ln = 0; voff = 1024; gam = gamq; bet = betq; }
    }
    int n0w = n0 + (wn << 6);
    int head = (n0w - voff) >> 6;

    float c[4][8][4];
    #pragma unroll
    for (int mf = 0; mf < 4; mf++)
        #pragma unroll
        for (int nf = 0; nf < 8; nf++)
            #pragma unroll
            for (int i = 0; i < 4; i++) c[mf][nf][i] = 0.f;

    uint32_t as_u = smem_u32(As), bs_u = smem_u32(Bs);
    int ar = tid >> 3, ac = tid & 7;
    int br = tid >> 5, bc = tid & 31;
    const float* Ap = A + (size_t)(m0 + ar) * CC + (ac << 2);
    const float* Wp = W + (size_t)br * ld + n0 + (bc << 2);

    #pragma unroll
    for (int i = 0; i < 8; i++) {
        cp16(as_u + ((ar + (i << 4)) * 36 + (ac << 2)) * 4, Ap + (size_t)(i << 4) * CC);
        cp16(bs_u + ((br + (i << 2)) * 136 + (bc << 2)) * 4, Wp + (size_t)(i << 2) * ld);
    }
    cp_commit();

    for (int ch = 0; ch < 32; ch++) {
        int buf = ch & 1;
        if (ch < 31) {
            int k0 = (ch + 1) << 5;
            int ob = buf ^ 1;
            #pragma unroll
            for (int i = 0; i < 8; i++) {
                cp16(as_u + (((ob << 7) + ar + (i << 4)) * 36 + (ac << 2)) * 4,
                     Ap + (size_t)(i << 4) * CC + k0);
                cp16(bs_u + (((ob << 5) + br + (i << 2)) * 136 + (bc << 2)) * 4,
                     Wp + (size_t)(k0 + (i << 2)) * ld);
            }
            cp_commit();
            cp_wait1();
        } else {
            cp_wait0();
        }
        __syncthreads();

        float (*Ab)[36]  = &As[buf << 7];
        float (*Bb)[136] = &Bs[buf << 5];
        #pragma unroll
        for (int ks = 0; ks < 4; ks++) {
            int k8 = ks << 3;
            uint32_t a[4][4];
            #pragma unroll
            for (int mf = 0; mf < 4; mf++) {
                int r = (wm << 6) + (mf << 4) + grp;
                a[mf][0] = __float_as_uint(Ab[r][k8 + l4]);
                a[mf][1] = __float_as_uint(Ab[r + 8][k8 + l4]);
                a[mf][2] = __float_as_uint(Ab[r][k8 + l4 + 4]);
                a[mf][3] = __float_as_uint(Ab[r + 8][k8 + l4 + 4]);
            }
            #pragma unroll
            for (int nf = 0; nf < 8; nf++) {
                int n = (wn << 6) + (nf << 3) + grp;
                uint32_t b[2];
                b[0] = __float_as_uint(Bb[k8 + l4][n]);
                b[1] = __float_as_uint(Bb[k8 + l4 + 4][n]);
                #pragma unroll
                for (int mf = 0; mf < 4; mf++)
                    mma8(c[mf][nf], a[mf], b);
            }
        }
        __syncthreads();
    }

    const float SC = 0.18033688011112042f;   // 0.125 * log2(e)
    #pragma unroll
    for (int mf = 0; mf < 4; mf++) {
        float s0 = 0.f, s1 = 0.f, t0 = 0.f, t1 = 0.f;
        #pragma unroll
        for (int nf = 0; nf < 8; nf++) {
            int col = (nf << 3) + (l4 << 1);
            float b0 = bias[n0w + col], b1 = bias[n0w + col + 1];
            c[mf][nf][0] += b0; c[mf][nf][1] += b1;
            c[mf][nf][2] += b0; c[mf][nf][3] += b1;
            s0 += c[mf][nf][0] + c[mf][nf][1];
            s1 += c[mf][nf][2] + c[mf][nf][3];
            t0 += c[mf][nf][0] * c[mf][nf][0] + c[mf][nf][1] * c[mf][nf][1];
            t1 += c[mf][nf][2] * c[mf][nf][2] + c[mf][nf][3] * c[mf][nf][3];
        }
        #pragma unroll
        for (int off = 1; off <= 2; off <<= 1) {
            s0 += __shfl_xor_sync(0xffffffffu, s0, off);
            s1 += __shfl_xor_sync(0xffffffffu, s1, off);
            t0 += __shfl_xor_sync(0xffffffffu, t0, off);
            t1 += __shfl_xor_sync(0xffffffffu, t1, off);
        }
        float mean0 = 0.f, mean1 = 0.f, inv0 = 1.f, inv1 = 1.f;
        if (do_ln) {
            mean0 = s0 * 0.015625f;
            mean1 = s1 * 0.015625f;
            inv0 = rsqrtf(t0 * 0.015625f - mean0 * mean0 + 1e-5f);
            inv1 = rsqrtf(t1 * 0.015625f - mean1 * mean1 + 1e-5f);
        }

        int r0 = (wm << 6) + (mf << 4) + grp;
        int m = m0 + r0;
        int b = m >> 11, nseq = m & 2047;
        size_t base0 = (((size_t)(b * HH + head)) * NN + nseq) * DD;
        size_t base1 = base0 + (size_t)8 * DD;
        #pragma unroll
        for (int nf = 0; nf < 8; nf++) {
            int col = (nf << 3) + (l4 << 1);
            float y0 = c[mf][nf][0], y1 = c[mf][nf][1];
            float y2 = c[mf][nf][2], y3 = c[mf][nf][3];
            if (do_ln) {
                float g0 = gam[col], g1 = gam[col + 1];
                float e0 = bet[col], e1 = bet[col + 1];
                y0 = (y0 - mean0) * inv0 * g0 + e0;
                y1 = (y1 - mean0) * inv0 * g1 + e1;
                y2 = (y2 - mean1) * inv1 * g0 + e0;
                y3 = (y3 - mean1) * inv1 * g1 + e1;
            }
            if (is_q) { y0 *= SC; y1 *= SC; y2 *= SC; y3 *= SC; }
            *(float2*)&Out[base0 + col] = make_float2(f2tf(y0), f2tf(y1));
            *(float2*)&Out[base1 + col] = make_float2(f2tf(y2), f2tf(y3));
        }
    }
}

// ---------------------------------------------------------------------------
// Flash attention (tf32 MMA), unnormalized exp2 accumulation (post-LN scores
// are bounded). Key-permuted K tile ([0,4,1,5,2,6,3,7] per 8-group) makes the
// S-fragment directly reusable as the PV A-fragment ({c0,c2,c1,c3}) with zero
// shuffles; V unpermuted. K/V double-buffered: 2 barriers + 1 wait per iter.
// 104 KB smem -> 2 CTAs/SM.
// ---------------------------------------------------------------------------
#define QS_F (128*68)
#define KS_F (64*68)
#define VS_F (64*72)
#define ATTN_SMEM ((QS_F + 2*KS_F + 2*VS_F) * 4)   // 106496 bytes

__global__ __launch_bounds__(128, 2) void attn_kernel(float* __restrict__ out)
{
    extern __shared__ float sm[];
    float (*Qs)[68] = (float(*)[68])sm;                    // 128x68
    float* Ksb = sm + QS_F;                                // 2 x 64x68
    float* Vsb = sm + QS_F + 2 * KS_F;                     // 2 x 64x72

    int tid = threadIdx.x;
    int wid = tid >> 5, lane = tid & 31;
    int grp = lane >> 2, l4 = lane & 3;
    int bh = blockIdx.y, qt = blockIdx.x;
    int mb = wid << 5;

    const float* qb = g_q + (size_t)bh * (NN * 64) + (size_t)qt * (128 * 64);
    const float* kb = g_k + (size_t)bh * (NN * 64);
    const float* vb = g_v + (size_t)bh * (NN * 64);

    uint32_t qs_u = smem_u32(Qs), ks_u = smem_u32(Ksb), vs_u = smem_u32(Vsb);
    int lr = tid >> 4, lch = tid & 15;
    int slr = ((lr & 3) << 1) | (lr >> 2);   // key permutation within 8-group

    // prologue: Q + K0/V0 (group A), then K1/V1 (group B)
    #pragma unroll
    for (int i = 0; i < 8; i++) {
        int r = lr + (i << 3);
        cp16(qs_u + r * 272 + (lch << 4), qb + r * 64 + (lch << 2));
        cp16(qs_u + (r + 64) * 272 + (lch << 4), qb + (r + 64) * 64 + (lch << 2));
        cp16(ks_u + ((i << 3) + slr) * 272 + (lch << 4), kb + r * 64 + (lch << 2));
        cp16(vs_u + r * 288 + (lch << 4), vb + r * 64 + (lch << 2));
    }
    cp_commit();
    #pragma unroll
    for (int i = 0; i < 8; i++) {
        int r = lr + (i << 3);
        cp16(ks_u + (KS_F + ((i << 3) + slr) * 68 + (lch << 2)) * 4, kb + 4096 + r * 64 + (lch << 2));
        cp16(vs_u + (VS_F + r * 72 + (lch << 2)) * 4, vb + 4096 + r * 64 + (lch << 2));
    }
    cp_commit();
    cp_wait1();        // group A complete
    __syncthreads();

    float o[2][8][4];
    #pragma unroll
    for (int mf = 0; mf < 2; mf++)
        #pragma unroll
        for (int df = 0; df < 8; df++)
            #pragma unroll
            for (int i = 0; i < 4; i++) o[mf][df][i] = 0.f;
    float l_i[4] = {0.f, 0.f, 0.f, 0.f};   // per-thread partial row sums

    for (int kt = 0; kt < 32; kt++) {
        int buf = kt & 1;
        const float* Ks = Ksb + buf * KS_F;   // [64][68]
        const float* Vs = Vsb + buf * VS_F;   // [64][72]

        // S = Q @ K^T (log2 domain; K columns key-permuted per 8-group)
        float s[2][8][4];
        #pragma unroll
        for (int mf = 0; mf < 2; mf++)
            #pragma unroll
            for (int nf = 0; nf < 8; nf++)
                #pragma unroll
                for (int i = 0; i < 4; i++) s[mf][nf][i] = 0.f;

        #pragma unroll
        for (int ks8 = 0; ks8 < 8; ks8++) {
            int k8 = ks8 << 3;
            uint32_t a[2][4], b[8][2];
            #pragma unroll
            for (int mf = 0; mf < 2; mf++) {
                int r = mb + (mf << 4) + grp;
                a[mf][0] = __float_as_uint(Qs[r][k8 + l4]);
                a[mf][1] = __float_as_uint(Qs[r + 8][k8 + l4]);
                a[mf][2] = __float_as_uint(Qs[r][k8 + l4 + 4]);
                a[mf][3] = __float_as_uint(Qs[r + 8][k8 + l4 + 4]);
            }
            #pragma unroll
            for (int nf = 0; nf < 8; nf++) {
                int n = (nf << 3) + grp;
                b[nf][0] = __float_as_uint(Ks[n * 68 + k8 + l4]);
                b[nf][1] = __float_as_uint(Ks[n * 68 + k8 + l4 + 4]);
            }
            #pragma unroll
            for (int mf = 0; mf < 2; mf++)
                #pragma unroll
                for (int nf = 0; nf < 8; nf++)
                    mma8(s[mf][nf], a[mf], b[nf]);
        }

        // p = exp2(s); per-thread row sums (no max, no rescale)
        #pragma unroll
        for (int mf = 0; mf < 2; mf++)
            #pragma unroll
            for (int nf = 0; nf < 8; nf++) {
                float p0 = ex2(s[mf][nf][0]);
                float p1 = ex2(s[mf][nf][1]);
                float p2 = ex2(s[mf][nf][2]);
                float p3 = ex2(s[mf][nf][3]);
                s[mf][nf][0] = p0; s[mf][nf][1] = p1;
                s[mf][nf][2] = p2; s[mf][nf][3] = p3;
                l_i[mf << 1]       += p0 + p1;
                l_i[(mf << 1) + 1] += p2 + p3;
            }

        // O += P @ V: S-fragment IS the A-fragment ({c0,c2,c1,c3}), no shuffles
        #pragma unroll
        for (int g = 0; g < 8; g++) {
            int k8 = g << 3;
            uint32_t b[8][2];
            #pragma unroll
            for (int df = 0; df < 8; df++) {
                int n = (df << 3) + grp;
                b[df][0] = __float_as_uint(Vs[(k8 + l4) * 72 + n]);
                b[df][1] = __float_as_uint(Vs[(k8 + l4 + 4) * 72 + n]);
            }
            #pragma unroll
            for (int mf = 0; mf < 2; mf++) {
                uint32_t a[4];
                a[0] = __float_as_uint(s[mf][g][0]);
                a[1] = __float_as_uint(s[mf][g][2]);
                a[2] = __float_as_uint(s[mf][g][1]);
                a[3] = __float_as_uint(s[mf][g][3]);
                #pragma unroll
                for (int df = 0; df < 8; df++)
                    mma8(o[mf][df], a, b[df]);
            }
        }

        if (kt < 31) {
            __syncthreads();       // all warps done with buf
            if (kt < 30) {
                const float* kn = kb + (kt + 2) * 4096;
                const float* vn = vb + (kt + 2) * 4096;
                uint32_t kdst = ks_u + buf * (KS_F * 4);
                uint32_t vdst = vs_u + buf * (VS_F * 4);
                #pragma unroll
                for (int i = 0; i < 8; i++) {
                    int r = lr + (i << 3);
                    cp16(kdst + ((i << 3) + slr) * 272 + (lch << 4), kn + r * 64 + (lch << 2));
                    cp16(vdst + r * 288 + (lch << 4), vn + r * 64 + (lch << 2));
                }
                cp_commit();
                cp_wait1();        // group kt+1 complete
            } else {
                cp_wait0();        // last pending group (kt+1 = 31)
            }
            __syncthreads();       // next buffer visible
        }
    }

    // epilogue: reduce row sums across quad, normalize, write out[b][n][h*64+d]
    #pragma unroll
    for (int si = 0; si < 4; si++) {
        l_i[si] += __shfl_xor_sync(0xffffffffu, l_i[si], 1);
        l_i[si] += __shfl_xor_sync(0xffffffffu, l_i[si], 2);
    }
    int b = bh >> 4, h = bh & 15;
    #pragma unroll
    for (int mf = 0; mf < 2; mf++) {
        #pragma unroll
        for (int rr = 0; rr < 2; rr++) {
            int si = (mf << 1) + rr;
            float inv = 1.f / l_i[si];
            int n = (qt << 7) + mb + (mf << 4) + grp + (rr << 3);
            size_t base = ((size_t)(b * NN + n)) * CC + (h << 6);
            #pragma unroll
            for (int df = 0; df < 8; df++) {
                int col = (df << 3) + (l4 << 1);
                float2 vo = make_float2(o[mf][df][rr * 2] * inv,
                                        o[mf][df][rr * 2 + 1] * inv);
                *(float2*)&out[base + col] = vo;
            }
        }
    }
}

// ---------------------------------------------------------------------------
extern "C" void kernel_launch(void* const* d_in, const int* in_sizes, int n_in,
                              void* d_out, int out_size)
{
    const float* x1   = (const float*)d_in[0];
    const float* x2   = (const float*)d_in[1];
    const float* wq   = (const float*)d_in[2];
    const float* bq   = (const float*)d_in[3];
    const float* wkv  = (const float*)d_in[4];
    const float* bkv  = (const float*)d_in[5];
    const float* gmq  = (const float*)d_in[6];
    const float* btq  = (const float*)d_in[7];
    const float* gmk  = (const float*)d_in[8];
    const float* btk  = (const float*)d_in[9];
    float* out = (float*)d_out;

    cudaFuncSetAttribute(attn_kernel, cudaFuncAttributeMaxDynamicSharedMemorySize, ATTN_SMEM);
    cudaFuncSetAttribute(proj_kernel, cudaFuncAttributeMaxDynamicSharedMemorySize, PROJ_SMEM);

    float *dx1t, *dx2t, *dwqt, *dwkvt;
    cudaGetSymbolAddress((void**)&dx1t, g_x1t);
    cudaGetSymbolAddress((void**)&dx2t, g_x2t);
    cudaGetSymbolAddress((void**)&dwqt, g_wqt);
    cudaGetSymbolAddress((void**)&dwkvt, g_wkvt);

    prep_kernel<<<(MM * CC / 4) / 256, 256>>>(x1, dx1t, MM * CC / 4);
    prep_kernel<<<(MM * CC / 4) / 256, 256>>>(x2, dx2t, MM * CC / 4);
    prep_kernel<<<(CC * CC / 4) / 256, 256>>>(wq, dwqt, CC * CC / 4);
    prep_kernel<<<(CC * 2 * CC / 4) / 256, 256>>>(wkv, dwkvt, CC * 2 * CC / 4);

    proj_kernel<<<dim3(24, MM / 128), 128, PROJ_SMEM>>>(bq, bkv, gmq, btq, gmk, btk);

    attn_kernel<<<dim3(NN / 128, BB * HH), 128, ATTN_SMEM>>>(out);
}